// round 3
// baseline (speedup 1.0000x reference)
#include <cuda_runtime.h>
#include <cstdint>

// ---------------------------------------------------------------------------
// GraphSAGE 2-layer, N=100000, E=1600000, 128 -> 128 -> 64.
//   layer1: h1 = relu( mean_agg(x) @ Wl1 + x @ Wr1 + b1 )
//   layer2: out = mean_agg(h1 @ Wl2) + h1 @ Wr2 + b2   (agg is linear)
// CSR build (no float atomics) -> warp-gather mean agg -> fused tf32 mma GEMM
// (double-buffered smem, 1 sync/ktile, h1 never leaves smem) -> final gather.
// ---------------------------------------------------------------------------

#define NNODES_MAX 100000
#define EDGES_MAX  1600000
#define SCAN_BLK   1024

__device__ int   d_not64;
__device__ int   d_deg[NNODES_MAX + 1];
__device__ int   d_rowptr[NNODES_MAX + 1];
__device__ int   d_cur[NNODES_MAX + 1];
__device__ int   d_bsums[1024];
__device__ int   d_adj[EDGES_MAX];
__device__ float d_agg1[(size_t)NNODES_MAX * 128];
__device__ float d_pq[(size_t)NNODES_MAX * 128];

// ---------------------------------------------------------------------------
// CSR build
// ---------------------------------------------------------------------------

// Zero degree array; detect edge dtype (int32 edge arrays have random nonzero
// odd 32-bit words; int64 with values < 2^31 has them all zero).
__global__ void k_detect_init(const unsigned int* __restrict__ w, int nchk, int n) {
    int i = blockIdx.x * blockDim.x + threadIdx.x;
    if (i < n) d_deg[i] = 0;
    if (i < nchk && w[2 * i + 1] != 0) d_not64 = 1;
}

__global__ void k_hist(const void* __restrict__ ei, int E) {
    int e = blockIdx.x * blockDim.x + threadIdx.x;
    if (e >= E) return;
    int dst = d_not64 ? ((const int*)ei)[E + e]
                      : (int)((const long long*)ei)[(long long)E + e];
    atomicAdd(&d_deg[dst], 1);
}

__global__ void k_scan1(int n) {
    __shared__ int wsum[32];
    int i = blockIdx.x * SCAN_BLK + threadIdx.x;
    int v = (i < n) ? d_deg[i] : 0;
    int lane = threadIdx.x & 31, w = threadIdx.x >> 5;
    int inc = v;
#pragma unroll
    for (int o = 1; o < 32; o <<= 1) {
        int t = __shfl_up_sync(0xffffffffu, inc, o);
        if (lane >= o) inc += t;
    }
    if (lane == 31) wsum[w] = inc;
    __syncthreads();
    if (w == 0) {
        int s = wsum[lane];
        int si = s;
#pragma unroll
        for (int o = 1; o < 32; o <<= 1) {
            int t = __shfl_up_sync(0xffffffffu, si, o);
            if (lane >= o) si += t;
        }
        wsum[lane] = si - s;
    }
    __syncthreads();
    int excl = inc - v + wsum[w];
    if (i < n) d_rowptr[i] = excl;
    if (threadIdx.x == SCAN_BLK - 1) d_bsums[blockIdx.x] = excl + v;
}

// parallel exclusive scan over <=1024 block sums (was a 5us serial loop)
__global__ void k_scan2(int nb) {
    __shared__ int wsum[32];
    int i = threadIdx.x;
    int v = (i < nb) ? d_bsums[i] : 0;
    int lane = i & 31, w = i >> 5;
    int inc = v;
#pragma unroll
    for (int o = 1; o < 32; o <<= 1) {
        int t = __shfl_up_sync(0xffffffffu, inc, o);
        if (lane >= o) inc += t;
    }
    if (lane == 31) wsum[w] = inc;
    __syncthreads();
    if (w == 0) {
        int s = wsum[lane];
        int si = s;
#pragma unroll
        for (int o = 1; o < 32; o <<= 1) {
            int t = __shfl_up_sync(0xffffffffu, si, o);
            if (lane >= o) si += t;
        }
        wsum[lane] = si - s;
    }
    __syncthreads();
    if (i < nb) d_bsums[i] = inc - v + wsum[w];
}

__global__ void k_scan3(int n) {
    int i = blockIdx.x * SCAN_BLK + threadIdx.x;
    if (i < n) {
        int v = d_rowptr[i] + d_bsums[blockIdx.x];
        d_rowptr[i] = v;
        d_cur[i] = v;
    }
}

__global__ void k_scatter(const void* __restrict__ ei, int E) {
    int e = blockIdx.x * blockDim.x + threadIdx.x;
    if (e >= E) return;
    int src, dst;
    if (d_not64) {
        const int* p = (const int*)ei;
        src = p[e];
        dst = p[E + e];
    } else {
        const long long* p = (const long long*)ei;
        src = (int)p[e];
        dst = (int)p[(long long)E + e];
    }
    int pos = atomicAdd(&d_cur[dst], 1);
    d_adj[pos] = src;
}

// ---------------------------------------------------------------------------
// Aggregation (warp per node)
// ---------------------------------------------------------------------------

__global__ void k_agg128(const float* __restrict__ feat, int n) {
    int gw = (blockIdx.x * blockDim.x + threadIdx.x) >> 5;
    if (gw >= n) return;
    int lane = threadIdx.x & 31;
    int start = d_rowptr[gw], deg = d_deg[gw];
    const float4* base = (const float4*)feat;
    float ax = 0.f, ay = 0.f, az = 0.f, aw = 0.f;
    int j = 0;
    for (; j + 4 <= deg; j += 4) {
        int n0 = d_adj[start + j + 0];
        int n1 = d_adj[start + j + 1];
        int n2 = d_adj[start + j + 2];
        int n3 = d_adj[start + j + 3];
        float4 v0 = __ldg(base + (size_t)n0 * 32 + lane);
        float4 v1 = __ldg(base + (size_t)n1 * 32 + lane);
        float4 v2 = __ldg(base + (size_t)n2 * 32 + lane);
        float4 v3 = __ldg(base + (size_t)n3 * 32 + lane);
        ax += v0.x + v1.x + v2.x + v3.x;
        ay += v0.y + v1.y + v2.y + v3.y;
        az += v0.z + v1.z + v2.z + v3.z;
        aw += v0.w + v1.w + v2.w + v3.w;
    }
    for (; j < deg; j++) {
        int nb = d_adj[start + j];
        float4 v = __ldg(base + (size_t)nb * 32 + lane);
        ax += v.x; ay += v.y; az += v.z; aw += v.w;
    }
    float inv = 1.0f / (float)(deg > 0 ? deg : 1);
    ((float4*)d_agg1)[(size_t)gw * 32 + lane] =
        make_float4(ax * inv, ay * inv, az * inv, aw * inv);
}

// out = mean_agg(p) + q + b2  with pq = [p(64) | q(64)] per row.
__global__ void k_final(float* __restrict__ out, const float* __restrict__ b2, int n) {
    int gw = (blockIdx.x * blockDim.x + threadIdx.x) >> 5;
    if (gw >= n) return;
    int lane = threadIdx.x & 31;
    int start = d_rowptr[gw], deg = d_deg[gw];
    const float* pq = d_pq;
    float ax = 0.f, ay = 0.f;
    int j = 0;
    for (; j + 4 <= deg; j += 4) {
        int n0 = d_adj[start + j + 0];
        int n1 = d_adj[start + j + 1];
        int n2 = d_adj[start + j + 2];
        int n3 = d_adj[start + j + 3];
        float2 v0 = __ldg((const float2*)(pq + (size_t)n0 * 128) + lane);
        float2 v1 = __ldg((const float2*)(pq + (size_t)n1 * 128) + lane);
        float2 v2 = __ldg((const float2*)(pq + (size_t)n2 * 128) + lane);
        float2 v3 = __ldg((const float2*)(pq + (size_t)n3 * 128) + lane);
        ax += v0.x + v1.x + v2.x + v3.x;
        ay += v0.y + v1.y + v2.y + v3.y;
    }
    for (; j < deg; j++) {
        int nb = d_adj[start + j];
        float2 v = __ldg((const float2*)(pq + (size_t)nb * 128) + lane);
        ax += v.x; ay += v.y;
    }
    float inv = 1.0f / (float)(deg > 0 ? deg : 1);
    float2 q = *(const float2*)(pq + (size_t)gw * 128 + 64 + 2 * lane);
    float2 bb = *(const float2*)(b2 + 2 * lane);
    float2 r;
    r.x = ax * inv + q.x + bb.x;
    r.y = ay * inv + q.y + bb.y;
    *(float2*)(out + (size_t)gw * 64 + 2 * lane) = r;
}

// ---------------------------------------------------------------------------
// Fused tf32 GEMM, double-buffered smem, 1 __syncthreads per ktile.
//  phase1: acc = [agg1 | x](K=256) @ [Wl1;Wr1]; h1 = relu(acc+b1) -> tf32 smem
//  phase2: pq = h1(K=128) @ [Wl2 | Wr2]
// smem word layout:
//   [0,4352)       Bs0 (phase1 buf0 B / phase2 buf0 B)   stride 136
//   [4352,8960)    As0 (phase1 buf0 A)                   stride 36
//   [8960,13312)   Bs1 (phase1 buf1 B)                   stride 136
//   [13312,17920)  As1 (phase1 buf1 A)                   stride 36
//   [4352,21248)   As2 (phase2 A = h1, 128x132)          stride 132
//   [21248,25600)  Bs2 (phase2 buf1 B)                   stride 136
// ---------------------------------------------------------------------------

#define BS_STRIDE 136
#define AS_STRIDE 36
#define AS2_STRIDE 132
#define OFF_BS0 0
#define OFF_AS0 4352
#define OFF_BS1 8960
#define OFF_AS1 13312
#define OFF_AS2 4352
#define OFF_BS2 21248
#define SMEM_WORDS 25600
#define SMEM_BYTES (SMEM_WORDS * 4)

__device__ __forceinline__ uint32_t f2tf32(float f) {
    uint32_t u;
    asm("cvt.rna.tf32.f32 %0, %1;" : "=r"(u) : "f"(f));
    return u;
}

__device__ __forceinline__ void mma_tf32(float c[4],
                                         uint32_t a0, uint32_t a1, uint32_t a2, uint32_t a3,
                                         uint32_t b0, uint32_t b1) {
    asm volatile(
        "mma.sync.aligned.m16n8k8.row.col.f32.tf32.tf32.f32 "
        "{%0,%1,%2,%3},{%4,%5,%6,%7},{%8,%9},{%0,%1,%2,%3};"
        : "+f"(c[0]), "+f"(c[1]), "+f"(c[2]), "+f"(c[3])
        : "r"(a0), "r"(a1), "r"(a2), "r"(a3), "r"(b0), "r"(b1));
}

__global__ __launch_bounds__(256, 2) void k_fused(
    const float* __restrict__ A0, const float* __restrict__ A1,
    const float* __restrict__ W1l, const float* __restrict__ W1r,
    const float* __restrict__ b1,
    const float* __restrict__ W2l, const float* __restrict__ W2r,
    float* __restrict__ pq, int M) {
    extern __shared__ uint32_t smem[];
    uint32_t* const as2 = smem + OFF_AS2;

    const int tid = threadIdx.x;
    const int lane = tid & 31;
    const int warp = tid >> 5;
    const int wm = warp >> 1;
    const int wn = warp & 1;
    const int g = lane >> 2;
    const int t = lane & 3;
    const int row0 = blockIdx.x * 128;

    const int la_r[4] = {(0 * 256 + tid) >> 3, (1 * 256 + tid) >> 3,
                         (2 * 256 + tid) >> 3, (3 * 256 + tid) >> 3};
    const int la_c = (tid & 7) * 4;
    const int lb_r[4] = {(0 * 256 + tid) >> 5, (1 * 256 + tid) >> 5,
                         (2 * 256 + tid) >> 5, (3 * 256 + tid) >> 5};
    const int lb_c = (tid & 31) * 4;

    float acc[2][8][4];
#pragma unroll
    for (int mi = 0; mi < 2; mi++)
#pragma unroll
        for (int ni = 0; ni < 8; ni++)
#pragma unroll
            for (int r = 0; r < 4; r++) acc[mi][ni][r] = 0.f;

    float4 rA[4], rB[4];

    // initial loads: ktile 0
#pragma unroll
    for (int v = 0; v < 4; v++) {
        int grow = row0 + la_r[v];
        rA[v] = make_float4(0.f, 0.f, 0.f, 0.f);
        if (grow < M) rA[v] = *(const float4*)(A0 + (size_t)grow * 128 + la_c);
        rB[v] = *(const float4*)(W1l + (size_t)lb_r[v] * 128 + lb_c);
    }

    // ----- phase 1: K = 256, 8 ktiles, double-buffered, 1 sync/ktile -----
    for (int kt = 0; kt < 8; kt++) {
        uint32_t* As = smem + ((kt & 1) ? OFF_AS1 : OFF_AS0);
        uint32_t* Bs = smem + ((kt & 1) ? OFF_BS1 : OFF_BS0);
#pragma unroll
        for (int v = 0; v < 4; v++) {
            uint32_t* d = As + la_r[v] * AS_STRIDE + la_c;
            d[0] = f2tf32(rA[v].x); d[1] = f2tf32(rA[v].y);
            d[2] = f2tf32(rA[v].z); d[3] = f2tf32(rA[v].w);
            uint32_t* e = Bs + lb_r[v] * BS_STRIDE + lb_c;
            e[0] = f2tf32(rB[v].x); e[1] = f2tf32(rB[v].y);
            e[2] = f2tf32(rB[v].z); e[3] = f2tf32(rB[v].w);
        }
        if (kt < 7) {
            int kt1 = kt + 1;
#pragma unroll
            for (int v = 0; v < 4; v++) {
                int grow = row0 + la_r[v];
                int gk = kt1 * 32 + la_c;
                rA[v] = make_float4(0.f, 0.f, 0.f, 0.f);
                if (grow < M) {
                    const float* src = (gk < 128)
                        ? (A0 + (size_t)grow * 128 + gk)
                        : (A1 + (size_t)grow * 128 + (gk - 128));
                    rA[v] = *(const float4*)src;
                }
                int wk = kt1 * 32 + lb_r[v];
                const float* wsrc = (wk < 128)
                    ? (W1l + (size_t)wk * 128 + lb_c)
                    : (W1r + (size_t)(wk - 128) * 128 + lb_c);
                rB[v] = *(const float4*)wsrc;
            }
        }
        __syncthreads();
#pragma unroll
        for (int ks = 0; ks < 4; ks++) {
            int kb = ks * 8;
            uint32_t af[2][4];
#pragma unroll
            for (int mi = 0; mi < 2; mi++) {
                int rb = wm * 32 + mi * 16;
                af[mi][0] = As[(rb + g) * AS_STRIDE + kb + t];
                af[mi][1] = As[(rb + g + 8) * AS_STRIDE + kb + t];
                af[mi][2] = As[(rb + g) * AS_STRIDE + kb + t + 4];
                af[mi][3] = As[(rb + g + 8) * AS_STRIDE + kb + t + 4];
            }
#pragma unroll
            for (int ni = 0; ni < 8; ni++) {
                int cn = wn * 64 + ni * 8 + g;
                uint32_t b0 = Bs[(kb + t) * BS_STRIDE + cn];
                uint32_t b1v = Bs[(kb + t + 4) * BS_STRIDE + cn];
                mma_tf32(acc[0][ni], af[0][0], af[0][1], af[0][2], af[0][3], b0, b1v);
                mma_tf32(acc[1][ni], af[1][0], af[1][1], af[1][2], af[1][3], b0, b1v);
            }
        }
        // no trailing sync (double buffer)
    }

    // prefetch W2 ktile 0 (overlaps epilogue)
#pragma unroll
    for (int v = 0; v < 4; v++) {
        const float* wsrc = (lb_c < 64) ? (W2l + (size_t)lb_r[v] * 64 + lb_c)
                                        : (W2r + (size_t)lb_r[v] * 64 + (lb_c - 64));
        rB[v] = *(const float4*)wsrc;
    }

    // all MMA(7) reads (buf1 aliases As2) must finish before As2 writes
    __syncthreads();

    // phase-1 epilogue: h1 = relu(acc + b1) -> tf32 As2
#pragma unroll
    for (int mi = 0; mi < 2; mi++) {
#pragma unroll
        for (int ni = 0; ni < 8; ni++) {
            int rr = wm * 32 + mi * 16 + g;
            int cc = wn * 64 + ni * 8 + 2 * t;
            float bb0 = b1[cc], bb1 = b1[cc + 1];
            as2[rr * AS2_STRIDE + cc]           = f2tf32(fmaxf(acc[mi][ni][0] + bb0, 0.f));
            as2[rr * AS2_STRIDE + cc + 1]       = f2tf32(fmaxf(acc[mi][ni][1] + bb1, 0.f));
            as2[(rr + 8) * AS2_STRIDE + cc]     = f2tf32(fmaxf(acc[mi][ni][2] + bb0, 0.f));
            as2[(rr + 8) * AS2_STRIDE + cc + 1] = f2tf32(fmaxf(acc[mi][ni][3] + bb1, 0.f));
        }
    }
#pragma unroll
    for (int mi = 0; mi < 2; mi++)
#pragma unroll
        for (int ni = 0; ni < 8; ni++)
#pragma unroll
            for (int r = 0; r < 4; r++) acc[mi][ni][r] = 0.f;

    // ----- phase 2: K = 128, 4 ktiles, double-buffered B, 1 sync/ktile -----
    for (int kt = 0; kt < 4; kt++) {
        uint32_t* Bs = smem + ((kt & 1) ? OFF_BS2 : OFF_BS0);
#pragma unroll
        for (int v = 0; v < 4; v++) {
            uint32_t* e = Bs + lb_r[v] * BS_STRIDE + lb_c;
            e[0] = f2tf32(rB[v].x); e[1] = f2tf32(rB[v].y);
            e[2] = f2tf32(rB[v].z); e[3] = f2tf32(rB[v].w);
        }
        if (kt < 3) {
            int wk1 = (kt + 1) * 32;
#pragma unroll
            for (int v = 0; v < 4; v++) {
                int wk = wk1 + lb_r[v];
                const float* wsrc = (lb_c < 64)
                    ? (W2l + (size_t)wk * 64 + lb_c)
                    : (W2r + (size_t)wk * 64 + (lb_c - 64));
                rB[v] = *(const float4*)wsrc;
            }
        }
        __syncthreads();
        int kofs = kt * 32;
#pragma unroll
        for (int ks = 0; ks < 4; ks++) {
            int kb = ks * 8;
            uint32_t af[2][4];
#pragma unroll
            for (int mi = 0; mi < 2; mi++) {
                int rb = wm * 32 + mi * 16;
                af[mi][0] = as2[(rb + g) * AS2_STRIDE + kofs + kb + t];
                af[mi][1] = as2[(rb + g + 8) * AS2_STRIDE + kofs + kb + t];
                af[mi][2] = as2[(rb + g) * AS2_STRIDE + kofs + kb + t + 4];
                af[mi][3] = as2[(rb + g + 8) * AS2_STRIDE + kofs + kb + t + 4];
            }
#pragma unroll
            for (int ni = 0; ni < 8; ni++) {
                int cn = wn * 64 + ni * 8 + g;
                uint32_t b0 = Bs[(kb + t) * BS_STRIDE + cn];
                uint32_t b1v = Bs[(kb + t + 4) * BS_STRIDE + cn];
                mma_tf32(acc[0][ni], af[0][0], af[0][1], af[0][2], af[0][3], b0, b1v);
                mma_tf32(acc[1][ni], af[1][0], af[1][1], af[1][2], af[1][3], b0, b1v);
            }
        }
    }

    // phase-2 epilogue: write pq
#pragma unroll
    for (int mi = 0; mi < 2; mi++) {
#pragma unroll
        for (int ni = 0; ni < 8; ni++) {
            int r0 = row0 + wm * 32 + mi * 16 + g;
            int cc = wn * 64 + ni * 8 + 2 * t;
            if (r0 < M)
                *(float2*)(pq + (size_t)r0 * 128 + cc) =
                    make_float2(acc[mi][ni][0], acc[mi][ni][1]);
            if (r0 + 8 < M)
                *(float2*)(pq + (size_t)(r0 + 8) * 128 + cc) =
                    make_float2(acc[mi][ni][2], acc[mi][ni][3]);
        }
    }
}

// ---------------------------------------------------------------------------
// Launch
// ---------------------------------------------------------------------------

extern "C" void kernel_launch(void* const* d_in, const int* in_sizes, int n_in,
                              void* d_out, int out_size) {
    const float* x   = (const float*)d_in[0];
    const void*  ei  = d_in[1];
    const float* Wl1 = (const float*)d_in[2];
    const float* Wr1 = (const float*)d_in[3];
    const float* b1  = (const float*)d_in[4];
    const float* Wl2 = (const float*)d_in[5];
    const float* Wr2 = (const float*)d_in[6];
    const float* b2  = (const float*)d_in[7];
    float* out = (float*)d_out;

    int n = in_sizes[0] / 128;
    int E = in_sizes[1] / 2;

    float* agg1;  cudaGetSymbolAddress((void**)&agg1, d_agg1);
    float* pq;    cudaGetSymbolAddress((void**)&pq, d_pq);
    void* not64p; cudaGetSymbolAddress(&not64p, d_not64);

    static int smem_set = 0;
    if (!smem_set) {
        cudaFuncSetAttribute(k_fused, cudaFuncAttributeMaxDynamicSharedMemorySize,
                             SMEM_BYTES);
        smem_set = 1;
    }

    int nb = (n + SCAN_BLK - 1) / SCAN_BLK;

    cudaMemsetAsync(not64p, 0, 4);
    k_detect_init<<<(n + 255) / 256, 256>>>((const unsigned int*)ei, 4096, n);
    k_hist<<<(E + 255) / 256, 256>>>(ei, E);
    k_scan1<<<nb, SCAN_BLK>>>(n);
    k_scan2<<<1, 1024>>>(nb);
    k_scan3<<<nb, SCAN_BLK>>>(n);
    k_scatter<<<(E + 255) / 256, 256>>>(ei, E);

    k_agg128<<<(n * 32 + 255) / 256, 256>>>(x, n);
    k_fused<<<(n + 127) / 128, 256, SMEM_BYTES>>>(agg1, x, Wl1, Wr1, b1,
                                                  Wl2, Wr2, pq, n);
    k_final<<<(n * 32 + 255) / 256, 256>>>(out, b2, n);
}

// round 4
// speedup vs baseline: 1.0615x; 1.0615x over previous
#include <cuda_runtime.h>
#include <cuda_fp16.h>
#include <cstdint>

// ---------------------------------------------------------------------------
// GraphSAGE 2-layer, N=100000, E=1600000, 128 -> 128 -> 64.
//   layer1: h1 = relu( mean_agg(x) @ Wl1 + x @ Wr1 + b1 )
//   layer2: out = mean_agg(h1 @ Wl2) + h1 @ Wr2 + b2   (agg is linear)
// CSR build (no float atomics) -> fp16 warp-gather mean agg -> fused tf32 mma
// GEMM (R2-winning single-buffer structure, h1 stays in smem; p written fp16,
// q fp32) -> final fp16 gather + residual + bias.
// ---------------------------------------------------------------------------

#define NNODES_MAX 100000
#define EDGES_MAX  1600000
#define SCAN_BLK   1024

__device__ int     d_not64;
__device__ int     d_deg[NNODES_MAX + 1];
__device__ int     d_rowptr[NNODES_MAX + 1];
__device__ int     d_cur[NNODES_MAX + 1];
__device__ int     d_bsums[1024];
__device__ int     d_adj[EDGES_MAX];
__device__ __half  d_x16[(size_t)NNODES_MAX * 128];
__device__ float   d_agg1[(size_t)NNODES_MAX * 128];
__device__ __half  d_p16[(size_t)NNODES_MAX * 64];
__device__ float   d_q[(size_t)NNODES_MAX * 64];

// ---------------------------------------------------------------------------
// Pre-pass: x -> fp16, zero degree array, detect edge dtype.
// (int32 edge arrays have random nonzero odd 32-bit words; int64 < 2^31 no.)
// ---------------------------------------------------------------------------

__global__ void k_pre(const float* __restrict__ x, const unsigned int* __restrict__ w,
                      int n, int nchk) {
    int i = blockIdx.x * blockDim.x + threadIdx.x;
    int total = n * 32;                       // one float4 per thread
    if (i < total) {
        float4 v = __ldg((const float4*)x + i);
        __half2 h0 = __floats2half2_rn(v.x, v.y);
        __half2 h1 = __floats2half2_rn(v.z, v.w);
        uint2 u;
        u.x = *(const unsigned int*)&h0;
        u.y = *(const unsigned int*)&h1;
        ((uint2*)d_x16)[i] = u;
    }
    if (i < n) d_deg[i] = 0;
    if (i < nchk && w[2 * i + 1] != 0) d_not64 = 1;
}

// ---------------------------------------------------------------------------
// CSR build
// ---------------------------------------------------------------------------

__global__ void k_hist(const void* __restrict__ ei, int E) {
    int e = blockIdx.x * blockDim.x + threadIdx.x;
    if (e >= E) return;
    int dst = d_not64 ? ((const int*)ei)[E + e]
                      : (int)((const long long*)ei)[(long long)E + e];
    atomicAdd(&d_deg[dst], 1);
}

__global__ void k_scan1(int n) {
    __shared__ int wsum[32];
    int i = blockIdx.x * SCAN_BLK + threadIdx.x;
    int v = (i < n) ? d_deg[i] : 0;
    int lane = threadIdx.x & 31, w = threadIdx.x >> 5;
    int inc = v;
#pragma unroll
    for (int o = 1; o < 32; o <<= 1) {
        int t = __shfl_up_sync(0xffffffffu, inc, o);
        if (lane >= o) inc += t;
    }
    if (lane == 31) wsum[w] = inc;
    __syncthreads();
    if (w == 0) {
        int s = wsum[lane];
        int si = s;
#pragma unroll
        for (int o = 1; o < 32; o <<= 1) {
            int t = __shfl_up_sync(0xffffffffu, si, o);
            if (lane >= o) si += t;
        }
        wsum[lane] = si - s;
    }
    __syncthreads();
    int excl = inc - v + wsum[w];
    if (i < n) d_rowptr[i] = excl;
    if (threadIdx.x == SCAN_BLK - 1) d_bsums[blockIdx.x] = excl + v;
}

// Each block redundantly sums bsums[0..blockIdx) (<=1024 values) — removes the
// separate grid=1 scan kernel (which cost ~5us of pure launch latency).
__global__ void k_scan3(int n) {
    __shared__ int partial[32];
    __shared__ int offs;
    int b = blockIdx.x;
    int lane = threadIdx.x & 31, w = threadIdx.x >> 5;
    int v = ((int)threadIdx.x < b) ? d_bsums[threadIdx.x] : 0;
#pragma unroll
    for (int o = 16; o > 0; o >>= 1) v += __shfl_down_sync(0xffffffffu, v, o);
    if (lane == 0) partial[w] = v;
    __syncthreads();
    if (threadIdx.x == 0) {
        int s = 0;
#pragma unroll
        for (int j = 0; j < 32; j++) s += partial[j];
        offs = s;
    }
    __syncthreads();
    int i = b * SCAN_BLK + threadIdx.x;
    if (i < n) {
        int t = d_rowptr[i] + offs;
        d_rowptr[i] = t;
        d_cur[i] = t;
    }
}

__global__ void k_scatter(const void* __restrict__ ei, int E) {
    int e = blockIdx.x * blockDim.x + threadIdx.x;
    if (e >= E) return;
    int src, dst;
    if (d_not64) {
        const int* p = (const int*)ei;
        src = p[e];
        dst = p[E + e];
    } else {
        const long long* p = (const long long*)ei;
        src = (int)p[e];
        dst = (int)p[(long long)E + e];
    }
    int pos = atomicAdd(&d_cur[dst], 1);
    d_adj[pos] = src;
}

// ---------------------------------------------------------------------------
// Layer-1 aggregation: warp per node, fp16 features, fp32 accumulate.
// Row = 128 halves = 256B; lane loads uint2 (4 halves) -> 128B*2 per warp/row.
// ---------------------------------------------------------------------------

__global__ void k_agg16(int n) {
    int gw = (blockIdx.x * blockDim.x + threadIdx.x) >> 5;
    if (gw >= n) return;
    int lane = threadIdx.x & 31;
    int start = d_rowptr[gw], deg = d_deg[gw];
    const uint2* base = (const uint2*)d_x16;    // 32 uint2 per row
    float ax = 0.f, ay = 0.f, az = 0.f, aw = 0.f;
    int j = 0;
    for (; j + 4 <= deg; j += 4) {
        int n0 = d_adj[start + j + 0];
        int n1 = d_adj[start + j + 1];
        int n2 = d_adj[start + j + 2];
        int n3 = d_adj[start + j + 3];
        uint2 u0 = __ldg(base + (size_t)n0 * 32 + lane);
        uint2 u1 = __ldg(base + (size_t)n1 * 32 + lane);
        uint2 u2 = __ldg(base + (size_t)n2 * 32 + lane);
        uint2 u3 = __ldg(base + (size_t)n3 * 32 + lane);
#pragma unroll
        for (int q = 0; q < 4; q++) {
            uint2 u = (q == 0) ? u0 : (q == 1) ? u1 : (q == 2) ? u2 : u3;
            float2 f0 = __half22float2(*(const __half2*)&u.x);
            float2 f1 = __half22float2(*(const __half2*)&u.y);
            ax += f0.x; ay += f0.y; az += f1.x; aw += f1.y;
        }
    }
    for (; j < deg; j++) {
        int nb = d_adj[start + j];
        uint2 u = __ldg(base + (size_t)nb * 32 + lane);
        float2 f0 = __half22float2(*(const __half2*)&u.x);
        float2 f1 = __half22float2(*(const __half2*)&u.y);
        ax += f0.x; ay += f0.y; az += f1.x; aw += f1.y;
    }
    float inv = 1.0f / (float)(deg > 0 ? deg : 1);
    ((float4*)d_agg1)[(size_t)gw * 32 + lane] =
        make_float4(ax * inv, ay * inv, az * inv, aw * inv);
}

// out = mean_agg(p16) + q + b2.  p16 row = 64 halves = 128B; lane loads uint.
__global__ void k_final16(float* __restrict__ out, const float* __restrict__ b2, int n) {
    int gw = (blockIdx.x * blockDim.x + threadIdx.x) >> 5;
    if (gw >= n) return;
    int lane = threadIdx.x & 31;
    int start = d_rowptr[gw], deg = d_deg[gw];
    const unsigned int* base = (const unsigned int*)d_p16;  // 32 uints per row
    float ax = 0.f, ay = 0.f;
    int j = 0;
    for (; j + 4 <= deg; j += 4) {
        int n0 = d_adj[start + j + 0];
        int n1 = d_adj[start + j + 1];
        int n2 = d_adj[start + j + 2];
        int n3 = d_adj[start + j + 3];
        unsigned int u0 = __ldg(base + (size_t)n0 * 32 + lane);
        unsigned int u1 = __ldg(base + (size_t)n1 * 32 + lane);
        unsigned int u2 = __ldg(base + (size_t)n2 * 32 + lane);
        unsigned int u3 = __ldg(base + (size_t)n3 * 32 + lane);
        float2 f0 = __half22float2(*(const __half2*)&u0);
        float2 f1 = __half22float2(*(const __half2*)&u1);
        float2 f2 = __half22float2(*(const __half2*)&u2);
        float2 f3 = __half22float2(*(const __half2*)&u3);
        ax += f0.x + f1.x + f2.x + f3.x;
        ay += f0.y + f1.y + f2.y + f3.y;
    }
    for (; j < deg; j++) {
        int nb = d_adj[start + j];
        unsigned int u = __ldg(base + (size_t)nb * 32 + lane);
        float2 f = __half22float2(*(const __half2*)&u);
        ax += f.x; ay += f.y;
    }
    float inv = 1.0f / (float)(deg > 0 ? deg : 1);
    float2 q = *(const float2*)(d_q + (size_t)gw * 64 + 2 * lane);
    float2 bb = *(const float2*)(b2 + 2 * lane);
    float2 r;
    r.x = ax * inv + q.x + bb.x;
    r.y = ay * inv + q.y + bb.y;
    *(float2*)(out + (size_t)gw * 64 + 2 * lane) = r;
}

// ---------------------------------------------------------------------------
// Fused tf32 GEMM (R2-winning structure: single buffer, static strides,
// register prefetch of next ktile, 2 syncs/ktile, 85KB smem, 2 blocks/SM).
//  phase1: acc = [agg1 | x](K=256) @ [Wl1;Wr1]; h1 = relu(acc+b1) -> tf32 smem
//  phase2: [p|q] = h1(K=128) @ [Wl2 | Wr2]; p -> fp16 d_p16, q -> fp32 d_q
// ---------------------------------------------------------------------------

#define BS_STRIDE 136
#define AS_STRIDE 36
#define AS2_STRIDE 132
#define SMEM_WORDS (32 * BS_STRIDE + 128 * AS2_STRIDE)
#define SMEM_BYTES (SMEM_WORDS * 4)

__device__ __forceinline__ uint32_t f2tf32(float f) {
    uint32_t u;
    asm("cvt.rna.tf32.f32 %0, %1;" : "=r"(u) : "f"(f));
    return u;
}

__device__ __forceinline__ void mma_tf32(float c[4],
                                         uint32_t a0, uint32_t a1, uint32_t a2, uint32_t a3,
                                         uint32_t b0, uint32_t b1) {
    asm volatile(
        "mma.sync.aligned.m16n8k8.row.col.f32.tf32.tf32.f32 "
        "{%0,%1,%2,%3},{%4,%5,%6,%7},{%8,%9},{%0,%1,%2,%3};"
        : "+f"(c[0]), "+f"(c[1]), "+f"(c[2]), "+f"(c[3])
        : "r"(a0), "r"(a1), "r"(a2), "r"(a3), "r"(b0), "r"(b1));
}

__global__ __launch_bounds__(256, 2) void k_fused(
    const float* __restrict__ A0, const float* __restrict__ A1,
    const float* __restrict__ W1l, const float* __restrict__ W1r,
    const float* __restrict__ b1,
    const float* __restrict__ W2l, const float* __restrict__ W2r,
    int M) {
    extern __shared__ uint32_t smem[];
    uint32_t (*Bs)[BS_STRIDE] = (uint32_t(*)[BS_STRIDE])smem;
    uint32_t (*As)[AS_STRIDE] = (uint32_t(*)[AS_STRIDE])(smem + 32 * BS_STRIDE);
    uint32_t (*As2)[AS2_STRIDE] = (uint32_t(*)[AS2_STRIDE])(smem + 32 * BS_STRIDE);

    const int tid = threadIdx.x;
    const int lane = tid & 31;
    const int warp = tid >> 5;
    const int wm = warp >> 1;
    const int wn = warp & 1;
    const int g = lane >> 2;
    const int t = lane & 3;
    const int row0 = blockIdx.x * 128;

    const int la_r[4] = {(0 * 256 + tid) >> 3, (1 * 256 + tid) >> 3,
                         (2 * 256 + tid) >> 3, (3 * 256 + tid) >> 3};
    const int la_c = (tid & 7) * 4;
    const int lb_r[4] = {(0 * 256 + tid) >> 5, (1 * 256 + tid) >> 5,
                         (2 * 256 + tid) >> 5, (3 * 256 + tid) >> 5};
    const int lb_c = (tid & 31) * 4;

    float acc[2][8][4];
#pragma unroll
    for (int mi = 0; mi < 2; mi++)
#pragma unroll
        for (int ni = 0; ni < 8; ni++)
#pragma unroll
            for (int r = 0; r < 4; r++) acc[mi][ni][r] = 0.f;

    float4 rA[4], rB[4];

#pragma unroll
    for (int v = 0; v < 4; v++) {
        int grow = row0 + la_r[v];
        rA[v] = make_float4(0.f, 0.f, 0.f, 0.f);
        if (grow < M) rA[v] = *(const float4*)(A0 + (size_t)grow * 128 + la_c);
        rB[v] = *(const float4*)(W1l + (size_t)lb_r[v] * 128 + lb_c);
    }

    // ----- phase 1: K = 256, 8 ktiles -----
    for (int kt = 0; kt < 8; kt++) {
#pragma unroll
        for (int v = 0; v < 4; v++) {
            uint32_t* d = &As[la_r[v]][la_c];
            d[0] = f2tf32(rA[v].x); d[1] = f2tf32(rA[v].y);
            d[2] = f2tf32(rA[v].z); d[3] = f2tf32(rA[v].w);
            uint32_t* e = &Bs[lb_r[v]][lb_c];
            e[0] = f2tf32(rB[v].x); e[1] = f2tf32(rB[v].y);
            e[2] = f2tf32(rB[v].z); e[3] = f2tf32(rB[v].w);
        }
        if (kt < 7) {
            int kt1 = kt + 1;
#pragma unroll
            for (int v = 0; v < 4; v++) {
                int grow = row0 + la_r[v];
                int gk = kt1 * 32 + la_c;
                rA[v] = make_float4(0.f, 0.f, 0.f, 0.f);
                if (grow < M) {
                    const float* src = (gk < 128)
                        ? (A0 + (size_t)grow * 128 + gk)
                        : (A1 + (size_t)grow * 128 + (gk - 128));
                    rA[v] = *(const float4*)src;
                }
                int wk = kt1 * 32 + lb_r[v];
                const float* wsrc = (wk < 128)
                    ? (W1l + (size_t)wk * 128 + lb_c)
                    : (W1r + (size_t)(wk - 128) * 128 + lb_c);
                rB[v] = *(const float4*)wsrc;
            }
        }
        __syncthreads();
#pragma unroll
        for (int ks = 0; ks < 4; ks++) {
            int kb = ks * 8;
            uint32_t af[2][4];
#pragma unroll
            for (int mi = 0; mi < 2; mi++) {
                int rb = wm * 32 + mi * 16;
                af[mi][0] = As[rb + g][kb + t];
                af[mi][1] = As[rb + g + 8][kb + t];
                af[mi][2] = As[rb + g][kb + t + 4];
                af[mi][3] = As[rb + g + 8][kb + t + 4];
            }
#pragma unroll
            for (int ni = 0; ni < 8; ni++) {
                int cn = wn * 64 + ni * 8 + g;
                uint32_t b0 = Bs[kb + t][cn];
                uint32_t b1v = Bs[kb + t + 4][cn];
                mma_tf32(acc[0][ni], af[0][0], af[0][1], af[0][2], af[0][3], b0, b1v);
                mma_tf32(acc[1][ni], af[1][0], af[1][1], af[1][2], af[1][3], b0, b1v);
            }
        }
        __syncthreads();
    }

    // prefetch W2 ktile 0 (overlaps epilogue)
#pragma unroll
    for (int v = 0; v < 4; v++) {
        const float* wsrc = (lb_c < 64) ? (W2l + (size_t)lb_r[v] * 64 + lb_c)
                                        : (W2r + (size_t)lb_r[v] * 64 + (lb_c - 64));
        rB[v] = *(const float4*)wsrc;
    }

    // phase-1 epilogue: h1 = relu(acc + b1) -> tf32 As2
#pragma unroll
    for (int mi = 0; mi < 2; mi++) {
#pragma unroll
        for (int ni = 0; ni < 8; ni++) {
            int rr = wm * 32 + mi * 16 + g;
            int cc = wn * 64 + ni * 8 + 2 * t;
            float bb0 = b1[cc], bb1 = b1[cc + 1];
            As2[rr][cc]         = f2tf32(fmaxf(acc[mi][ni][0] + bb0, 0.f));
            As2[rr][cc + 1]     = f2tf32(fmaxf(acc[mi][ni][1] + bb1, 0.f));
            As2[rr + 8][cc]     = f2tf32(fmaxf(acc[mi][ni][2] + bb0, 0.f));
            As2[rr + 8][cc + 1] = f2tf32(fmaxf(acc[mi][ni][3] + bb1, 0.f));
        }
    }
#pragma unroll
    for (int mi = 0; mi < 2; mi++)
#pragma unroll
        for (int ni = 0; ni < 8; ni++)
#pragma unroll
            for (int r = 0; r < 4; r++) acc[mi][ni][r] = 0.f;

    // ----- phase 2: K = 128, 4 ktiles -----
    for (int kt = 0; kt < 4; kt++) {
#pragma unroll
        for (int v = 0; v < 4; v++) {
            uint32_t* e = &Bs[lb_r[v]][lb_c];
            e[0] = f2tf32(rB[v].x); e[1] = f2tf32(rB[v].y);
            e[2] = f2tf32(rB[v].z); e[3] = f2tf32(rB[v].w);
        }
        if (kt < 3) {
            int wk1 = (kt + 1) * 32;
#pragma unroll
            for (int v = 0; v < 4; v++) {
                int wk = wk1 + lb_r[v];
                const float* wsrc = (lb_c < 64)
                    ? (W2l + (size_t)wk * 64 + lb_c)
                    : (W2r + (size_t)wk * 64 + (lb_c - 64));
                rB[v] = *(const float4*)wsrc;
            }
        }
        __syncthreads();
        int kofs = kt * 32;
#pragma unroll
        for (int ks = 0; ks < 4; ks++) {
            int kb = ks * 8;
            uint32_t af[2][4];
#pragma unroll
            for (int mi = 0; mi < 2; mi++) {
                int rb = wm * 32 + mi * 16;
                af[mi][0] = As2[rb + g][kofs + kb + t];
                af[mi][1] = As2[rb + g + 8][kofs + kb + t];
                af[mi][2] = As2[rb + g][kofs + kb + t + 4];
                af[mi][3] = As2[rb + g + 8][kofs + kb + t + 4];
            }
#pragma unroll
            for (int ni = 0; ni < 8; ni++) {
                int cn = wn * 64 + ni * 8 + g;
                uint32_t b0 = Bs[kb + t][cn];
                uint32_t b1v = Bs[kb + t + 4][cn];
                mma_tf32(acc[0][ni], af[0][0], af[0][1], af[0][2], af[0][3], b0, b1v);
                mma_tf32(acc[1][ni], af[1][0], af[1][1], af[1][2], af[1][3], b0, b1v);
            }
        }
        __syncthreads();
    }

    // phase-2 epilogue: wn==0 warps hold p (cols 0..63) -> fp16; wn==1 -> q fp32
#pragma unroll
    for (int mi = 0; mi < 2; mi++) {
#pragma unroll
        for (int ni = 0; ni < 8; ni++) {
            int r0 = row0 + wm * 32 + mi * 16 + g;
            int cc = wn * 64 + ni * 8 + 2 * t;
            if (wn == 0) {
                __half2 h0 = __floats2half2_rn(acc[mi][ni][0], acc[mi][ni][1]);
                __half2 h1 = __floats2half2_rn(acc[mi][ni][2], acc[mi][ni][3]);
                if (r0 < M)
                    *(__half2*)(d_p16 + (size_t)r0 * 64 + cc) = h0;
                if (r0 + 8 < M)
                    *(__half2*)(d_p16 + (size_t)(r0 + 8) * 64 + cc) = h1;
            } else {
                int cq = cc - 64;
                if (r0 < M)
                    *(float2*)(d_q + (size_t)r0 * 64 + cq) =
                        make_float2(acc[mi][ni][0], acc[mi][ni][1]);
                if (r0 + 8 < M)
                    *(float2*)(d_q + (size_t)(r0 + 8) * 64 + cq) =
                        make_float2(acc[mi][ni][2], acc[mi][ni][3]);
            }
        }
    }
}

// ---------------------------------------------------------------------------
// Launch
// ---------------------------------------------------------------------------

extern "C" void kernel_launch(void* const* d_in, const int* in_sizes, int n_in,
                              void* d_out, int out_size) {
    const float* x   = (const float*)d_in[0];
    const void*  ei  = d_in[1];
    const float* Wl1 = (const float*)d_in[2];
    const float* Wr1 = (const float*)d_in[3];
    const float* b1  = (const float*)d_in[4];
    const float* Wl2 = (const float*)d_in[5];
    const float* Wr2 = (const float*)d_in[6];
    const float* b2  = (const float*)d_in[7];
    float* out = (float*)d_out;

    int n = in_sizes[0] / 128;
    int E = in_sizes[1] / 2;

    float* agg1;  cudaGetSymbolAddress((void**)&agg1, d_agg1);
    void* not64p; cudaGetSymbolAddress(&not64p, d_not64);

    static int smem_set = 0;
    if (!smem_set) {
        cudaFuncSetAttribute(k_fused, cudaFuncAttributeMaxDynamicSharedMemorySize,
                             SMEM_BYTES);
        smem_set = 1;
    }

    int nb = (n + SCAN_BLK - 1) / SCAN_BLK;

    cudaMemsetAsync(not64p, 0, 4);
    k_pre<<<(n * 32 + 255) / 256, 256>>>(x, (const unsigned int*)ei, n, 4096);
    k_hist<<<(E + 255) / 256, 256>>>(ei, E);
    k_scan1<<<nb, SCAN_BLK>>>(n);
    k_scan3<<<nb, SCAN_BLK>>>(n);
    k_scatter<<<(E + 255) / 256, 256>>>(ei, E);

    k_agg16<<<(n * 32 + 255) / 256, 256>>>(n);
    k_fused<<<(n + 127) / 128, 256, SMEM_BYTES>>>(agg1, x, Wl1, Wr1, b1,
                                                  Wl2, Wr2, n);
    k_final16<<<(n * 32 + 255) / 256, 256>>>(out, b2, n);
}

// round 5
// speedup vs baseline: 1.0820x; 1.0193x over previous
#include <cuda_runtime.h>
#include <cuda_fp16.h>
#include <cstdint>

// ---------------------------------------------------------------------------
// GraphSAGE 2-layer, N=100000, E=1600000, 128 -> 128 -> 64.
//   layer1: h1 = relu( mean_agg(x) @ Wl1 + x @ Wr1 + b1 )
//   layer2: out = mean_agg(h1 @ Wl2) + h1 @ Wr2 + b2   (agg is linear)
// 6 launches: prehist (x->fp16 + dtype + histogram), lookback-scan, scatter,
// fp16 warp-gather agg, fused tf32 GEMM (h1 stays in smem), final gather.
// d_deg / d_bsums / d_bflag are zeroed by the END of k_final16 so the next
// run starts clean (zero-init at module load covers run #1) — removes the
// memset + init kernels entirely.
// ---------------------------------------------------------------------------

#define NNODES_MAX 100000
#define EDGES_MAX  1600000
#define SCAN_BLK   1024

__device__ int     d_deg[NNODES_MAX + 1];     // zero at entry (see k_final16)
__device__ int     d_rowptr[NNODES_MAX + 1];
__device__ int     d_cur[NNODES_MAX + 1];
__device__ int     d_bsums[128];              // zero at entry
__device__ int     d_bflag[128];              // zero at entry
__device__ int     d_adj[EDGES_MAX];
__device__ __half  d_x16[(size_t)NNODES_MAX * 128];
__device__ float   d_agg1[(size_t)NNODES_MAX * 128];
__device__ __half  d_p16[(size_t)NNODES_MAX * 64];
__device__ float   d_q[(size_t)NNODES_MAX * 64];

// Per-block edge-dtype detect: int32 edge arrays have random nonzero odd
// 32-bit words; int64 with values < 2^31 has them all zero. OR of 16 fixed
// odd words -> wrong with prob ~(1e-5)^16.
__device__ __forceinline__ int detect_not64_block(const void* ei) {
    __shared__ int s_not64;
    if (threadIdx.x == 0) {
        const unsigned int* w = (const unsigned int*)ei;
        unsigned int o = 0;
#pragma unroll
        for (int j = 1; j < 32; j += 2) o |= w[j];
        s_not64 = (o != 0);
    }
    __syncthreads();
    return s_not64;
}

// ---------------------------------------------------------------------------
// 1) x -> fp16  +  degree histogram (deg starts zeroed)
// ---------------------------------------------------------------------------

__global__ void k_prehist(const float* __restrict__ x, const void* __restrict__ ei,
                          int n, int E) {
    int not64 = detect_not64_block(ei);
    int i = blockIdx.x * blockDim.x + threadIdx.x;
    if (i < n * 32) {                          // one float4 -> uint2 per thread
        float4 v = __ldg((const float4*)x + i);
        __half2 h0 = __floats2half2_rn(v.x, v.y);
        __half2 h1 = __floats2half2_rn(v.z, v.w);
        uint2 u;
        u.x = *(const unsigned int*)&h0;
        u.y = *(const unsigned int*)&h1;
        ((uint2*)d_x16)[i] = u;
    }
    if (i < E) {
        int dst = not64 ? ((const int*)ei)[E + i]
                        : (int)((const long long*)ei)[(size_t)E + i];
        atomicAdd(&d_deg[dst], 1);
    }
}

// ---------------------------------------------------------------------------
// 2) single-pass exclusive scan (decoupled lookback over <=98 blocks,
//    all blocks resident simultaneously -> spin is deadlock-free)
// ---------------------------------------------------------------------------

__global__ void k_scan(int n) {
    __shared__ int wsum[32];
    __shared__ int s_off;
    int b = blockIdx.x;
    int i = b * SCAN_BLK + threadIdx.x;
    int v = (i < n) ? d_deg[i] : 0;
    int lane = threadIdx.x & 31, w = threadIdx.x >> 5;
    int inc = v;
#pragma unroll
    for (int o = 1; o < 32; o <<= 1) {
        int t = __shfl_up_sync(0xffffffffu, inc, o);
        if (lane >= o) inc += t;
    }
    if (lane == 31) wsum[w] = inc;
    __syncthreads();
    if (w == 0) {
        int s = wsum[lane];
        int si = s;
#pragma unroll
        for (int o = 1; o < 32; o <<= 1) {
            int t = __shfl_up_sync(0xffffffffu, si, o);
            if (lane >= o) si += t;
        }
        wsum[lane] = si - s;
    }
    __syncthreads();
    int excl = inc - v + wsum[w];

    // publish block total, then lookback
    if (threadIdx.x == SCAN_BLK - 1) {
        d_bsums[b] = excl + v;
        __threadfence();
        *((volatile int*)&d_bflag[b]) = 1;
    }
    if (w == 0) {
        int sum = 0;
        for (int j = lane; j < b; j += 32) {
            while (*((volatile int*)&d_bflag[j]) == 0) __nanosleep(50);
            sum += *((volatile int*)&d_bsums[j]);
        }
#pragma unroll
        for (int o = 16; o > 0; o >>= 1) sum += __shfl_down_sync(0xffffffffu, sum, o);
        if (lane == 0) s_off = sum;
    }
    __syncthreads();
    if (i < n) {
        int t = excl + s_off;
        d_rowptr[i] = t;
        d_cur[i] = t;
    }
}

// ---------------------------------------------------------------------------
// 3) scatter edges into CSR
// ---------------------------------------------------------------------------

__global__ void k_scatter(const void* __restrict__ ei, int E) {
    int not64 = detect_not64_block(ei);
    int e = blockIdx.x * blockDim.x + threadIdx.x;
    if (e >= E) return;
    int src, dst;
    if (not64) {
        const int* p = (const int*)ei;
        src = p[e];
        dst = p[E + e];
    } else {
        const long long* p = (const long long*)ei;
        src = (int)p[e];
        dst = (int)p[(size_t)E + e];
    }
    int pos = atomicAdd(&d_cur[dst], 1);
    d_adj[pos] = src;
}

// ---------------------------------------------------------------------------
// 4) layer-1 aggregation: warp/node, fp16 feats, 8 neighbors in flight
// ---------------------------------------------------------------------------

__global__ void k_agg16(int n) {
    int gw = (blockIdx.x * blockDim.x + threadIdx.x) >> 5;
    if (gw >= n) return;
    int lane = threadIdx.x & 31;
    int start = d_rowptr[gw], deg = d_deg[gw];
    const uint2* base = (const uint2*)d_x16;    // 32 uint2 per 128-half row
    float ax = 0.f, ay = 0.f, az = 0.f, aw = 0.f;
    int j = 0;
    for (; j + 8 <= deg; j += 8) {
        int idx[8];
#pragma unroll
        for (int q = 0; q < 8; q++) idx[q] = d_adj[start + j + q];
        uint2 u[8];
#pragma unroll
        for (int q = 0; q < 8; q++) u[q] = __ldg(base + (size_t)idx[q] * 32 + lane);
#pragma unroll
        for (int q = 0; q < 8; q++) {
            float2 f0 = __half22float2(*(const __half2*)&u[q].x);
            float2 f1 = __half22float2(*(const __half2*)&u[q].y);
            ax += f0.x; ay += f0.y; az += f1.x; aw += f1.y;
        }
    }
    for (; j < deg; j++) {
        int nb = d_adj[start + j];
        uint2 u = __ldg(base + (size_t)nb * 32 + lane);
        float2 f0 = __half22float2(*(const __half2*)&u.x);
        float2 f1 = __half22float2(*(const __half2*)&u.y);
        ax += f0.x; ay += f0.y; az += f1.x; aw += f1.y;
    }
    float inv = 1.0f / (float)(deg > 0 ? deg : 1);
    ((float4*)d_agg1)[(size_t)gw * 32 + lane] =
        make_float4(ax * inv, ay * inv, az * inv, aw * inv);
}

// ---------------------------------------------------------------------------
// 6) out = mean_agg(p16) + q + b2 ; also re-zeroes deg/bsums/bflag for the
//    next run.
// ---------------------------------------------------------------------------

__global__ void k_final16(float* __restrict__ out, const float* __restrict__ b2, int n) {
    int gw = (blockIdx.x * blockDim.x + threadIdx.x) >> 5;
    if (gw >= n) return;
    int lane = threadIdx.x & 31;
    int start = d_rowptr[gw], deg = d_deg[gw];
    const unsigned int* base = (const unsigned int*)d_p16;  // 32 uints per row
    float ax = 0.f, ay = 0.f;
    int j = 0;
    for (; j + 8 <= deg; j += 8) {
        int idx[8];
#pragma unroll
        for (int q = 0; q < 8; q++) idx[q] = d_adj[start + j + q];
        unsigned int u[8];
#pragma unroll
        for (int q = 0; q < 8; q++) u[q] = __ldg(base + (size_t)idx[q] * 32 + lane);
#pragma unroll
        for (int q = 0; q < 8; q++) {
            float2 f = __half22float2(*(const __half2*)&u[q]);
            ax += f.x; ay += f.y;
        }
    }
    for (; j < deg; j++) {
        int nb = d_adj[start + j];
        unsigned int u = __ldg(base + (size_t)nb * 32 + lane);
        float2 f = __half22float2(*(const __half2*)&u);
        ax += f.x; ay += f.y;
    }
    float inv = 1.0f / (float)(deg > 0 ? deg : 1);
    float2 q = *(const float2*)(d_q + (size_t)gw * 64 + 2 * lane);
    float2 bb = *(const float2*)(b2 + 2 * lane);
    float2 r;
    r.x = ax * inv + q.x + bb.x;
    r.y = ay * inv + q.y + bb.y;
    *(float2*)(out + (size_t)gw * 64 + 2 * lane) = r;

    // prep next run (deterministic across replays)
    if (lane == 0) d_deg[gw] = 0;
    if (blockIdx.x == 0 && threadIdx.x < 128) {
        d_bsums[threadIdx.x] = 0;
        d_bflag[threadIdx.x] = 0;
    }
}

// ---------------------------------------------------------------------------
// 5) fused tf32 GEMM (R2/R4-winning structure: single buffer, static strides,
// register prefetch of next ktile, 85KB smem, 2 blocks/SM).
//  phase1: acc = [agg1 | x](K=256) @ [Wl1;Wr1]; h1 = relu(acc+b1) -> tf32 smem
//  phase2: [p|q] = h1(K=128) @ [Wl2 | Wr2]; p -> fp16 d_p16, q -> fp32 d_q
// ---------------------------------------------------------------------------

#define BS_STRIDE 136
#define AS_STRIDE 36
#define AS2_STRIDE 132
#define SMEM_WORDS (32 * BS_STRIDE + 128 * AS2_STRIDE)
#define SMEM_BYTES (SMEM_WORDS * 4)

__device__ __forceinline__ uint32_t f2tf32(float f) {
    uint32_t u;
    asm("cvt.rna.tf32.f32 %0, %1;" : "=r"(u) : "f"(f));
    return u;
}

__device__ __forceinline__ void mma_tf32(float c[4],
                                         uint32_t a0, uint32_t a1, uint32_t a2, uint32_t a3,
                                         uint32_t b0, uint32_t b1) {
    asm volatile(
        "mma.sync.aligned.m16n8k8.row.col.f32.tf32.tf32.f32 "
        "{%0,%1,%2,%3},{%4,%5,%6,%7},{%8,%9},{%0,%1,%2,%3};"
        : "+f"(c[0]), "+f"(c[1]), "+f"(c[2]), "+f"(c[3])
        : "r"(a0), "r"(a1), "r"(a2), "r"(a3), "r"(b0), "r"(b1));
}

__global__ __launch_bounds__(256, 2) void k_fused(
    const float* __restrict__ A0, const float* __restrict__ A1,
    const float* __restrict__ W1l, const float* __restrict__ W1r,
    const float* __restrict__ b1,
    const float* __restrict__ W2l, const float* __restrict__ W2r,
    int M) {
    extern __shared__ uint32_t smem[];
    uint32_t (*Bs)[BS_STRIDE] = (uint32_t(*)[BS_STRIDE])smem;
    uint32_t (*As)[AS_STRIDE] = (uint32_t(*)[AS_STRIDE])(smem + 32 * BS_STRIDE);
    uint32_t (*As2)[AS2_STRIDE] = (uint32_t(*)[AS2_STRIDE])(smem + 32 * BS_STRIDE);

    const int tid = threadIdx.x;
    const int lane = tid & 31;
    const int warp = tid >> 5;
    const int wm = warp >> 1;
    const int wn = warp & 1;
    const int g = lane >> 2;
    const int t = lane & 3;
    const int row0 = blockIdx.x * 128;

    const int la_r[4] = {(0 * 256 + tid) >> 3, (1 * 256 + tid) >> 3,
                         (2 * 256 + tid) >> 3, (3 * 256 + tid) >> 3};
    const int la_c = (tid & 7) * 4;
    const int lb_r[4] = {(0 * 256 + tid) >> 5, (1 * 256 + tid) >> 5,
                         (2 * 256 + tid) >> 5, (3 * 256 + tid) >> 5};
    const int lb_c = (tid & 31) * 4;

    float acc[2][8][4];
#pragma unroll
    for (int mi = 0; mi < 2; mi++)
#pragma unroll
        for (int ni = 0; ni < 8; ni++)
#pragma unroll
            for (int r = 0; r < 4; r++) acc[mi][ni][r] = 0.f;

    float4 rA[4], rB[4];

#pragma unroll
    for (int v = 0; v < 4; v++) {
        int grow = row0 + la_r[v];
        rA[v] = make_float4(0.f, 0.f, 0.f, 0.f);
        if (grow < M) rA[v] = *(const float4*)(A0 + (size_t)grow * 128 + la_c);
        rB[v] = *(const float4*)(W1l + (size_t)lb_r[v] * 128 + lb_c);
    }

    // ----- phase 1: K = 256, 8 ktiles -----
    for (int kt = 0; kt < 8; kt++) {
#pragma unroll
        for (int v = 0; v < 4; v++) {
            uint32_t* d = &As[la_r[v]][la_c];
            d[0] = f2tf32(rA[v].x); d[1] = f2tf32(rA[v].y);
            d[2] = f2tf32(rA[v].z); d[3] = f2tf32(rA[v].w);
            uint32_t* e = &Bs[lb_r[v]][lb_c];
            e[0] = f2tf32(rB[v].x); e[1] = f2tf32(rB[v].y);
            e[2] = f2tf32(rB[v].z); e[3] = f2tf32(rB[v].w);
        }
        if (kt < 7) {
            int kt1 = kt + 1;
#pragma unroll
            for (int v = 0; v < 4; v++) {
                int grow = row0 + la_r[v];
                int gk = kt1 * 32 + la_c;
                rA[v] = make_float4(0.f, 0.f, 0.f, 0.f);
                if (grow < M) {
                    const float* src = (gk < 128)
                        ? (A0 + (size_t)grow * 128 + gk)
                        : (A1 + (size_t)grow * 128 + (gk - 128));
                    rA[v] = *(const float4*)src;
                }
                int wk = kt1 * 32 + lb_r[v];
                const float* wsrc = (wk < 128)
                    ? (W1l + (size_t)wk * 128 + lb_c)
                    : (W1r + (size_t)(wk - 128) * 128 + lb_c);
                rB[v] = *(const float4*)wsrc;
            }
        }
        __syncthreads();
#pragma unroll
        for (int ks = 0; ks < 4; ks++) {
            int kb = ks * 8;
            uint32_t af[2][4];
#pragma unroll
            for (int mi = 0; mi < 2; mi++) {
                int rb = wm * 32 + mi * 16;
                af[mi][0] = As[rb + g][kb + t];
                af[mi][1] = As[rb + g + 8][kb + t];
                af[mi][2] = As[rb + g][kb + t + 4];
                af[mi][3] = As[rb + g + 8][kb + t + 4];
            }
#pragma unroll
            for (int ni = 0; ni < 8; ni++) {
                int cn = wn * 64 + ni * 8 + g;
                uint32_t b0 = Bs[kb + t][cn];
                uint32_t b1v = Bs[kb + t + 4][cn];
                mma_tf32(acc[0][ni], af[0][0], af[0][1], af[0][2], af[0][3], b0, b1v);
                mma_tf32(acc[1][ni], af[1][0], af[1][1], af[1][2], af[1][3], b0, b1v);
            }
        }
        __syncthreads();
    }

    // prefetch W2 ktile 0 (overlaps epilogue)
#pragma unroll
    for (int v = 0; v < 4; v++) {
        const float* wsrc = (lb_c < 64) ? (W2l + (size_t)lb_r[v] * 64 + lb_c)
                                        : (W2r + (size_t)lb_r[v] * 64 + (lb_c - 64));
        rB[v] = *(const float4*)wsrc;
    }

    // phase-1 epilogue: h1 = relu(acc + b1) -> tf32 As2
#pragma unroll
    for (int mi = 0; mi < 2; mi++) {
#pragma unroll
        for (int ni = 0; ni < 8; ni++) {
            int rr = wm * 32 + mi * 16 + g;
            int cc = wn * 64 + ni * 8 + 2 * t;
            float bb0 = b1[cc], bb1 = b1[cc + 1];
            As2[rr][cc]         = f2tf32(fmaxf(acc[mi][ni][0] + bb0, 0.f));
            As2[rr][cc + 1]     = f2tf32(fmaxf(acc[mi][ni][1] + bb1, 0.f));
            As2[rr + 8][cc]     = f2tf32(fmaxf(acc[mi][ni][2] + bb0, 0.f));
            As2[rr + 8][cc + 1] = f2tf32(fmaxf(acc[mi][ni][3] + bb1, 0.f));
        }
    }
#pragma unroll
    for (int mi = 0; mi < 2; mi++)
#pragma unroll
        for (int ni = 0; ni < 8; ni++)
#pragma unroll
            for (int r = 0; r < 4; r++) acc[mi][ni][r] = 0.f;

    // ----- phase 2: K = 128, 4 ktiles -----
    for (int kt = 0; kt < 4; kt++) {
#pragma unroll
        for (int v = 0; v < 4; v++) {
            uint32_t* e = &Bs[lb_r[v]][lb_c];
            e[0] = f2tf32(rB[v].x); e[1] = f2tf32(rB[v].y);
            e[2] = f2tf32(rB[v].z); e[3] = f2tf32(rB[v].w);
        }
        if (kt < 3) {
            int wk1 = (kt + 1) * 32;
#pragma unroll
            for (int v = 0; v < 4; v++) {
                int wk = wk1 + lb_r[v];
                const float* wsrc = (lb_c < 64)
                    ? (W2l + (size_t)wk * 64 + lb_c)
                    : (W2r + (size_t)wk * 64 + (lb_c - 64));
                rB[v] = *(const float4*)wsrc;
            }
        }
        __syncthreads();
        int kofs = kt * 32;
#pragma unroll
        for (int ks = 0; ks < 4; ks++) {
            int kb = ks * 8;
            uint32_t af[2][4];
#pragma unroll
            for (int mi = 0; mi < 2; mi++) {
                int rb = wm * 32 + mi * 16;
                af[mi][0] = As2[rb + g][kofs + kb + t];
                af[mi][1] = As2[rb + g + 8][kofs + kb + t];
                af[mi][2] = As2[rb + g][kofs + kb + t + 4];
                af[mi][3] = As2[rb + g + 8][kofs + kb + t + 4];
            }
#pragma unroll
            for (int ni = 0; ni < 8; ni++) {
                int cn = wn * 64 + ni * 8 + g;
                uint32_t b0 = Bs[kb + t][cn];
                uint32_t b1v = Bs[kb + t + 4][cn];
                mma_tf32(acc[0][ni], af[0][0], af[0][1], af[0][2], af[0][3], b0, b1v);
                mma_tf32(acc[1][ni], af[1][0], af[1][1], af[1][2], af[1][3], b0, b1v);
            }
        }
        __syncthreads();
    }

    // phase-2 epilogue: wn==0 warps hold p (cols 0..63) -> fp16; wn==1 -> q fp32
#pragma unroll
    for (int mi = 0; mi < 2; mi++) {
#pragma unroll
        for (int ni = 0; ni < 8; ni++) {
            int r0 = row0 + wm * 32 + mi * 16 + g;
            int cc = wn * 64 + ni * 8 + 2 * t;
            if (wn == 0) {
                __half2 h0 = __floats2half2_rn(acc[mi][ni][0], acc[mi][ni][1]);
                __half2 h1 = __floats2half2_rn(acc[mi][ni][2], acc[mi][ni][3]);
                if (r0 < M)
                    *(__half2*)(d_p16 + (size_t)r0 * 64 + cc) = h0;
                if (r0 + 8 < M)
                    *(__half2*)(d_p16 + (size_t)(r0 + 8) * 64 + cc) = h1;
            } else {
                int cq = cc - 64;
                if (r0 < M)
                    *(float2*)(d_q + (size_t)r0 * 64 + cq) =
                        make_float2(acc[mi][ni][0], acc[mi][ni][1]);
                if (r0 + 8 < M)
                    *(float2*)(d_q + (size_t)(r0 + 8) * 64 + cq) =
                        make_float2(acc[mi][ni][2], acc[mi][ni][3]);
            }
        }
    }
}

// ---------------------------------------------------------------------------
// Launch
// ---------------------------------------------------------------------------

extern "C" void kernel_launch(void* const* d_in, const int* in_sizes, int n_in,
                              void* d_out, int out_size) {
    const float* x   = (const float*)d_in[0];
    const void*  ei  = d_in[1];
    const float* Wl1 = (const float*)d_in[2];
    const float* Wr1 = (const float*)d_in[3];
    const float* b1  = (const float*)d_in[4];
    const float* Wl2 = (const float*)d_in[5];
    const float* Wr2 = (const float*)d_in[6];
    const float* b2  = (const float*)d_in[7];
    float* out = (float*)d_out;

    int n = in_sizes[0] / 128;
    int E = in_sizes[1] / 2;

    float* agg1; cudaGetSymbolAddress((void**)&agg1, d_agg1);

    static int smem_set = 0;
    if (!smem_set) {
        cudaFuncSetAttribute(k_fused, cudaFuncAttributeMaxDynamicSharedMemorySize,
                             SMEM_BYTES);
        smem_set = 1;
    }

    int nb = (n + SCAN_BLK - 1) / SCAN_BLK;

    k_prehist<<<(n * 32 + 255) / 256, 256>>>(x, ei, n, E);   // launch 1
    k_scan<<<nb, SCAN_BLK>>>(n);                              // launch 2
    k_scatter<<<(E + 255) / 256, 256>>>(ei, E);               // launch 3
    k_agg16<<<(n * 32 + 255) / 256, 256>>>(n);                // launch 4 (profiled)
    k_fused<<<(n + 127) / 128, 256, SMEM_BYTES>>>(agg1, x, Wl1, Wr1, b1,
                                                  Wl2, Wr2, n);
    k_final16<<<(n * 32 + 255) / 256, 256>>>(out, b2, n);
}

// round 6
// speedup vs baseline: 1.3673x; 1.2637x over previous
#include <cuda_runtime.h>
#include <cuda_fp16.h>
#include <cstdint>

// ---------------------------------------------------------------------------
// GraphSAGE 2-layer, N=100000, E=1600000, 128 -> 128 -> 64.
//   layer1: h1 = relu( mean_agg(x) @ Wl1 + x @ Wr1 + b1 )
//   layer2: out = mean_agg(h1 @ Wl2) + h1 @ Wr2 + b2   (agg is linear)
// 5 launches:
//   1 k_prehist      x->fp16, W->fp16 k-paired transposed, degree histogram
//   2 k_scan_scatter lookback scan + grid barrier + CSR scatter
//   3 k_agg16        fp16 warp-gather mean agg -> fp16
//   4 k_fused        fp16 m16n8k16 mma GEMM, both layers, h1 stays in smem
//   5 k_final16      fp16 gather + residual + bias (+ reset state for replay)
// ---------------------------------------------------------------------------

#define NNODES_MAX 100000
#define EDGES_MAX  1600000
#define SCAN_BLK   1024

__device__ int     d_deg[NNODES_MAX + 1];     // zeroed by k_final16 for replay
__device__ int     d_rowptr[NNODES_MAX + 1];
__device__ int     d_cur[NNODES_MAX + 1];
__device__ int     d_bsums[128];              // zeroed by k_final16
__device__ int     d_bflag[128];              // zeroed by k_final16
__device__ int     d_barrier;                 // zeroed by k_final16
__device__ int     d_adj[EDGES_MAX];
__device__ __align__(16) __half  d_x16[(size_t)NNODES_MAX * 128];
__device__ __align__(16) __half  d_agg16[(size_t)NNODES_MAX * 128];
__device__ __align__(16) uint32_t d_w1c[128 * 128];  // [n][k2] half2, K=256
__device__ __align__(16) uint32_t d_w2c[128 * 64];   // [n][k2] half2, K=128
__device__ __align__(16) __half  d_p16[(size_t)NNODES_MAX * 64];
__device__ __align__(16) float   d_q[(size_t)NNODES_MAX * 64];

// int32 edge arrays have random nonzero odd 32-bit words; int64 (<2^31) no.
__device__ __forceinline__ int detect_not64_block(const void* ei) {
    __shared__ int s_not64;
    if (threadIdx.x == 0) {
        const unsigned int* w = (const unsigned int*)ei;
        unsigned int o = 0;
#pragma unroll
        for (int j = 1; j < 32; j += 2) o |= w[j];
        s_not64 = (o != 0);
    }
    __syncthreads();
    return s_not64;
}

// ---------------------------------------------------------------------------
// 1) x -> fp16; W1/W2 -> fp16 k-paired col-major; degree histogram
// ---------------------------------------------------------------------------

__global__ void k_prehist(const float* __restrict__ x, const void* __restrict__ ei,
                          const float* __restrict__ W1l, const float* __restrict__ W1r,
                          const float* __restrict__ W2l, const float* __restrict__ W2r,
                          int n, int E) {
    int not64 = detect_not64_block(ei);
    int i = blockIdx.x * blockDim.x + threadIdx.x;
    if (i < n * 32) {                          // one float4 -> uint2 per thread
        float4 v = __ldg((const float4*)x + i);
        __half2 h0 = __floats2half2_rn(v.x, v.y);
        __half2 h1 = __floats2half2_rn(v.z, v.w);
        uint2 u;
        u.x = *(const unsigned int*)&h0;
        u.y = *(const unsigned int*)&h1;
        ((uint2*)d_x16)[i] = u;
    }
    if (i < E) {
        int dst = not64 ? ((const int*)ei)[E + i]
                        : (int)((const long long*)ei)[(size_t)E + i];
        atomicAdd(&d_deg[dst], 1);
    }
    // W1c: [n=128][k2=128], k = 2*k2; k<128 from W1l, else W1r
    if (i < 128 * 128) {
        int nn = i >> 7, k2 = i & 127, k = k2 * 2;
        float f0, f1;
        if (k < 128) { f0 = W1l[k * 128 + nn]; f1 = W1l[(k + 1) * 128 + nn]; }
        else         { f0 = W1r[(k - 128) * 128 + nn]; f1 = W1r[(k - 127) * 128 + nn]; }
        __half2 h = __floats2half2_rn(f0, f1);
        d_w1c[i] = *(const uint32_t*)&h;
    } else if (i < 128 * 128 + 128 * 64) {
        // W2c: [n=128][k2=64]; n<64 from W2l, else W2r
        int j = i - 128 * 128;
        int nn = j >> 6, k2 = j & 63, k = k2 * 2;
        float f0, f1;
        if (nn < 64) { f0 = W2l[k * 64 + nn]; f1 = W2l[(k + 1) * 64 + nn]; }
        else         { f0 = W2r[k * 64 + (nn - 64)]; f1 = W2r[(k + 1) * 64 + (nn - 64)]; }
        __half2 h = __floats2half2_rn(f0, f1);
        d_w2c[j] = *(const uint32_t*)&h;
    }
}

// ---------------------------------------------------------------------------
// 2) lookback scan over block sums + grid barrier + CSR scatter (one kernel;
//    98 blocks, all resident -> spins are deadlock-free)
// ---------------------------------------------------------------------------

__global__ void k_scan_scatter(const void* __restrict__ ei, int n, int E) {
    int not64 = detect_not64_block(ei);
    __shared__ int wsum[32];
    __shared__ int s_off;
    int b = blockIdx.x;
    int i = b * SCAN_BLK + threadIdx.x;
    int v = (i < n) ? d_deg[i] : 0;
    int lane = threadIdx.x & 31, w = threadIdx.x >> 5;
    int inc = v;
#pragma unroll
    for (int o = 1; o < 32; o <<= 1) {
        int t = __shfl_up_sync(0xffffffffu, inc, o);
        if (lane >= o) inc += t;
    }
    if (lane == 31) wsum[w] = inc;
    __syncthreads();
    if (w == 0) {
        int s = wsum[lane];
        int si = s;
#pragma unroll
        for (int o = 1; o < 32; o <<= 1) {
            int t = __shfl_up_sync(0xffffffffu, si, o);
            if (lane >= o) si += t;
        }
        wsum[lane] = si - s;
    }
    __syncthreads();
    int excl = inc - v + wsum[w];

    if (threadIdx.x == SCAN_BLK - 1) {
        d_bsums[b] = excl + v;
        __threadfence();
        *((volatile int*)&d_bflag[b]) = 1;
    }
    if (w == 0) {
        int sum = 0;
        for (int j = lane; j < b; j += 32) {
            while (*((volatile int*)&d_bflag[j]) == 0) __nanosleep(50);
            sum += *((volatile int*)&d_bsums[j]);
        }
#pragma unroll
        for (int o = 16; o > 0; o >>= 1) sum += __shfl_down_sync(0xffffffffu, sum, o);
        if (lane == 0) s_off = sum;
    }
    __syncthreads();
    if (i < n) {
        int t = excl + s_off;
        d_rowptr[i] = t;
        d_cur[i] = t;
    }

    // grid barrier: all cur[] must be written before any scatter
    __syncthreads();
    if (threadIdx.x == 0) {
        __threadfence();
        atomicAdd(&d_barrier, 1);
        while (*((volatile int*)&d_barrier) < gridDim.x) __nanosleep(100);
    }
    __syncthreads();

    int stride = gridDim.x * blockDim.x;
    for (int e = b * SCAN_BLK + threadIdx.x; e < E; e += stride) {
        int src, dst;
        if (not64) {
            const int* p = (const int*)ei;
            src = p[e];
            dst = p[E + e];
        } else {
            const long long* p = (const long long*)ei;
            src = (int)p[e];
            dst = (int)p[(size_t)E + e];
        }
        int pos = atomicAdd(&d_cur[dst], 1);
        d_adj[pos] = src;
    }
}

// ---------------------------------------------------------------------------
// 3) layer-1 aggregation: warp/node, fp16 feats, fp32 accumulate, fp16 out
// ---------------------------------------------------------------------------

__global__ void k_agg16(int n) {
    int gw = (blockIdx.x * blockDim.x + threadIdx.x) >> 5;
    if (gw >= n) return;
    int lane = threadIdx.x & 31;
    int start = d_rowptr[gw], deg = d_deg[gw];
    const uint2* base = (const uint2*)d_x16;    // 32 uint2 per 128-half row
    float ax = 0.f, ay = 0.f, az = 0.f, aw = 0.f;
    int j = 0;
    for (; j + 8 <= deg; j += 8) {
        int idx[8];
#pragma unroll
        for (int q = 0; q < 8; q++) idx[q] = d_adj[start + j + q];
        uint2 u[8];
#pragma unroll
        for (int q = 0; q < 8; q++) u[q] = __ldg(base + (size_t)idx[q] * 32 + lane);
#pragma unroll
        for (int q = 0; q < 8; q++) {
            float2 f0 = __half22float2(*(const __half2*)&u[q].x);
            float2 f1 = __half22float2(*(const __half2*)&u[q].y);
            ax += f0.x; ay += f0.y; az += f1.x; aw += f1.y;
        }
    }
    for (; j < deg; j++) {
        int nb = d_adj[start + j];
        uint2 u = __ldg(base + (size_t)nb * 32 + lane);
        float2 f0 = __half22float2(*(const __half2*)&u.x);
        float2 f1 = __half22float2(*(const __half2*)&u.y);
        ax += f0.x; ay += f0.y; az += f1.x; aw += f1.y;
    }
    float inv = 1.0f / (float)(deg > 0 ? deg : 1);
    __half2 h0 = __floats2half2_rn(ax * inv, ay * inv);
    __half2 h1 = __floats2half2_rn(az * inv, aw * inv);
    uint2 u;
    u.x = *(const unsigned int*)&h0;
    u.y = *(const unsigned int*)&h1;
    ((uint2*)d_agg16)[(size_t)gw * 32 + lane] = u;
}

// ---------------------------------------------------------------------------
// 5) out = mean_agg(p16) + q + b2 ; resets device state for next replay
// ---------------------------------------------------------------------------

__global__ void k_final16(float* __restrict__ out, const float* __restrict__ b2, int n) {
    int gw = (blockIdx.x * blockDim.x + threadIdx.x) >> 5;
    if (gw >= n) return;
    int lane = threadIdx.x & 31;
    int start = d_rowptr[gw], deg = d_deg[gw];
    const unsigned int* base = (const unsigned int*)d_p16;  // 32 uints per row
    float ax = 0.f, ay = 0.f;
    int j = 0;
    for (; j + 8 <= deg; j += 8) {
        int idx[8];
#pragma unroll
        for (int q = 0; q < 8; q++) idx[q] = d_adj[start + j + q];
        unsigned int u[8];
#pragma unroll
        for (int q = 0; q < 8; q++) u[q] = __ldg(base + (size_t)idx[q] * 32 + lane);
#pragma unroll
        for (int q = 0; q < 8; q++) {
            float2 f = __half22float2(*(const __half2*)&u[q]);
            ax += f.x; ay += f.y;
        }
    }
    for (; j < deg; j++) {
        int nb = d_adj[start + j];
        unsigned int u = __ldg(base + (size_t)nb * 32 + lane);
        float2 f = __half22float2(*(const __half2*)&u);
        ax += f.x; ay += f.y;
    }
    float inv = 1.0f / (float)(deg > 0 ? deg : 1);
    float2 q = *(const float2*)(d_q + (size_t)gw * 64 + 2 * lane);
    float2 bb = *(const float2*)(b2 + 2 * lane);
    float2 r;
    r.x = ax * inv + q.x + bb.x;
    r.y = ay * inv + q.y + bb.y;
    *(float2*)(out + (size_t)gw * 64 + 2 * lane) = r;

    // prep next run (deterministic across replays)
    if (lane == 0) d_deg[gw] = 0;
    if (blockIdx.x == 0 && threadIdx.x < 128) {
        d_bsums[threadIdx.x] = 0;
        d_bflag[threadIdx.x] = 0;
        if (threadIdx.x == 0) d_barrier = 0;
    }
}

// ---------------------------------------------------------------------------
// 4) fused fp16 m16n8k16 GEMM. BM=128, BN=128, BK=32, 256 threads,
// warp tile 32x64, fragments pair-indexed (uint = half2 of adjacent k).
//  phase1: acc = [agg16 | x16](K=256) @ W1c; h1 = relu(acc+b1) -> fp16 smem
//  phase2: [p|q] = h1(K=128) @ W2c; p -> fp16 d_p16, q -> fp32 d_q
// smem (uints): A tile 128x20, B tile 128x20, A2 (h1) 128x68 = 13824 words.
// ---------------------------------------------------------------------------

#define AST   20
#define BST   20
#define A2ST  68
#define OFF_A 0
#define OFF_B (128 * AST)
#define OFF_A2 (OFF_B + 128 * BST)
#define SMEM_WORDS (OFF_A2 + 128 * A2ST)
#define SMEM_BYTES (SMEM_WORDS * 4)

__device__ __forceinline__ void mma_f16(float c[4],
                                        uint32_t a0, uint32_t a1, uint32_t a2, uint32_t a3,
                                        uint32_t b0, uint32_t b1) {
    asm volatile(
        "mma.sync.aligned.m16n8k16.row.col.f32.f16.f16.f32 "
        "{%0,%1,%2,%3},{%4,%5,%6,%7},{%8,%9},{%0,%1,%2,%3};"
        : "+f"(c[0]), "+f"(c[1]), "+f"(c[2]), "+f"(c[3])
        : "r"(a0), "r"(a1), "r"(a2), "r"(a3), "r"(b0), "r"(b1));
}

__global__ __launch_bounds__(256, 2) void k_fused(const float* __restrict__ b1, int M) {
    extern __shared__ uint32_t smem[];
    uint32_t* const As = smem + OFF_A;
    uint32_t* const Bs = smem + OFF_B;
    uint32_t* const A2 = smem + OFF_A2;

    const int tid = threadIdx.x;
    const int lane = tid & 31;
    const int warp = tid >> 5;
    const int wm = warp >> 1;          // 0..3: 32-row band
    const int wn = warp & 1;           // 0..1: 64-col band
    const int g = lane >> 2;
    const int t = lane & 3;
    const int row0 = blockIdx.x * 128;

    // tile-load coords: idx = v*256+tid over 512 uint4; row/n = idx>>2, c4 = idx&3
    const int lr[2] = {(0 * 256 + tid) >> 2, (1 * 256 + tid) >> 2};
    const int lc4 = tid & 3;

    const uint4* agg4 = (const uint4*)d_agg16;   // 16 uint4 per row
    const uint4* x4   = (const uint4*)d_x16;     // 16 uint4 per row
    const uint4* w1   = (const uint4*)d_w1c;     // 32 uint4 per n
    const uint4* w2   = (const uint4*)d_w2c;     // 16 uint4 per n

    float acc[2][8][4];
#pragma unroll
    for (int mi = 0; mi < 2; mi++)
#pragma unroll
        for (int ni = 0; ni < 8; ni++)
#pragma unroll
            for (int r = 0; r < 4; r++) acc[mi][ni][r] = 0.f;

    uint4 rA[2], rB[2];
    const uint4 z4 = make_uint4(0, 0, 0, 0);

    // prefetch ktile 0
#pragma unroll
    for (int v = 0; v < 2; v++) {
        int grow = row0 + lr[v];
        rA[v] = (grow < M) ? __ldg(agg4 + (size_t)grow * 16 + lc4) : z4;
        rB[v] = __ldg(w1 + lr[v] * 32 + lc4);
    }

    // ----- phase 1: K = 256, 8 ktiles of 32 halves -----
    for (int kt = 0; kt < 8; kt++) {
#pragma unroll
        for (int v = 0; v < 2; v++) {
            *(uint4*)(As + lr[v] * AST + lc4 * 4) = rA[v];
            *(uint4*)(Bs + lr[v] * BST + lc4 * 4) = rB[v];
        }
        if (kt < 7) {
            int kt1 = kt + 1;
#pragma unroll
            for (int v = 0; v < 2; v++) {
                int grow = row0 + lr[v];
                if (grow < M) {
                    rA[v] = (kt1 < 4)
                        ? __ldg(agg4 + (size_t)grow * 16 + kt1 * 4 + lc4)
                        : __ldg(x4 + (size_t)grow * 16 + (kt1 - 4) * 4 + lc4);
                } else rA[v] = z4;
                rB[v] = __ldg(w1 + lr[v] * 32 + kt1 * 4 + lc4);
            }
        }
        __syncthreads();
#pragma unroll
        for (int ks = 0; ks < 2; ks++) {
            int kb = ks * 8;
            uint32_t af[2][4];
#pragma unroll
            for (int mi = 0; mi < 2; mi++) {
                int rb = wm * 32 + mi * 16;
                af[mi][0] = As[(rb + g) * AST + kb + t];
                af[mi][1] = As[(rb + g + 8) * AST + kb + t];
                af[mi][2] = As[(rb + g) * AST + kb + t + 4];
                af[mi][3] = As[(rb + g + 8) * AST + kb + t + 4];
            }
#pragma unroll
            for (int ni = 0; ni < 8; ni++) {
                int cn = wn * 64 + ni * 8 + g;
                uint32_t b0 = Bs[cn * BST + kb + t];
                uint32_t b1v = Bs[cn * BST + kb + t + 4];
                mma_f16(acc[0][ni], af[0][0], af[0][1], af[0][2], af[0][3], b0, b1v);
                mma_f16(acc[1][ni], af[1][0], af[1][1], af[1][2], af[1][3], b0, b1v);
            }
        }
        __syncthreads();
    }

    // prefetch W2 ktile 0 (overlaps epilogue)
#pragma unroll
    for (int v = 0; v < 2; v++) rB[v] = __ldg(w2 + lr[v] * 16 + lc4);

    // phase-1 epilogue: h1 = relu(acc + b1) -> fp16 A2 (k-paired)
#pragma unroll
    for (int mi = 0; mi < 2; mi++) {
#pragma unroll
        for (int ni = 0; ni < 8; ni++) {
            int rr = wm * 32 + mi * 16 + g;
            int cc = wn * 64 + ni * 8 + 2 * t;
            int ci = cc >> 1;
            float bb0 = b1[cc], bb1 = b1[cc + 1];
            __half2 h0 = __floats2half2_rn(fmaxf(acc[mi][ni][0] + bb0, 0.f),
                                           fmaxf(acc[mi][ni][1] + bb1, 0.f));
            __half2 h1 = __floats2half2_rn(fmaxf(acc[mi][ni][2] + bb0, 0.f),
                                           fmaxf(acc[mi][ni][3] + bb1, 0.f));
            A2[rr * A2ST + ci] = *(const uint32_t*)&h0;
            A2[(rr + 8) * A2ST + ci] = *(const uint32_t*)&h1;
        }
    }
#pragma unroll
    for (int mi = 0; mi < 2; mi++)
#pragma unroll
        for (int ni = 0; ni < 8; ni++)
#pragma unroll
            for (int r = 0; r < 4; r++) acc[mi][ni][r] = 0.f;

    // ----- phase 2: K = 128, 4 ktiles -----
    for (int kt = 0; kt < 4; kt++) {
#pragma unroll
        for (int v = 0; v < 2; v++)
            *(uint4*)(Bs + lr[v] * BST + lc4 * 4) = rB[v];
        if (kt < 3) {
#pragma unroll
            for (int v = 0; v < 2; v++)
                rB[v] = __ldg(w2 + lr[v] * 16 + (kt + 1) * 4 + lc4);
        }
        __syncthreads();
        int kof = kt * 16;
#pragma unroll
        for (int ks = 0; ks < 2; ks++) {
            int kb = ks * 8;
            uint32_t af[2][4];
#pragma unroll
            for (int mi = 0; mi < 2; mi++) {
                int rb = wm * 32 + mi * 16;
                af[mi][0] = A2[(rb + g) * A2ST + kof + kb + t];
                af[mi][1] = A2[(rb + g + 8) * A2ST + kof + kb + t];
                af[mi][2] = A2[(rb + g) * A2ST + kof + kb + t + 4];
                af[mi][3] = A2[(rb + g + 8) * A2ST + kof + kb + t + 4];
            }
#pragma unroll
            for (int ni = 0; ni < 8; ni++) {
                int cn = wn * 64 + ni * 8 + g;
                uint32_t b0 = Bs[cn * BST + kb + t];
                uint32_t b1v = Bs[cn * BST + kb + t + 4];
                mma_f16(acc[0][ni], af[0][0], af[0][1], af[0][2], af[0][3], b0, b1v);
                mma_f16(acc[1][ni], af[1][0], af[1][1], af[1][2], af[1][3], b0, b1v);
            }
        }
        __syncthreads();
    }

    // phase-2 epilogue: wn==0 warps hold p (cols 0..63) -> fp16; wn==1 -> q fp32
#pragma unroll
    for (int mi = 0; mi < 2; mi++) {
#pragma unroll
        for (int ni = 0; ni < 8; ni++) {
            int r0 = row0 + wm * 32 + mi * 16 + g;
            int cc = wn * 64 + ni * 8 + 2 * t;
            if (wn == 0) {
                __half2 h0 = __floats2half2_rn(acc[mi][ni][0], acc[mi][ni][1]);
                __half2 h1 = __floats2half2_rn(acc[mi][ni][2], acc[mi][ni][3]);
                if (r0 < M)
                    *(__half2*)(d_p16 + (size_t)r0 * 64 + cc) = h0;
                if (r0 + 8 < M)
                    *(__half2*)(d_p16 + (size_t)(r0 + 8) * 64 + cc) = h1;
            } else {
                int cq = cc - 64;
                if (r0 < M)
                    *(float2*)(d_q + (size_t)r0 * 64 + cq) =
                        make_float2(acc[mi][ni][0], acc[mi][ni][1]);
                if (r0 + 8 < M)
                    *(float2*)(d_q + (size_t)(r0 + 8) * 64 + cq) =
                        make_float2(acc[mi][ni][2], acc[mi][ni][3]);
            }
        }
    }
}

// ---------------------------------------------------------------------------
// Launch
// ---------------------------------------------------------------------------

extern "C" void kernel_launch(void* const* d_in, const int* in_sizes, int n_in,
                              void* d_out, int out_size) {
    const float* x   = (const float*)d_in[0];
    const void*  ei  = d_in[1];
    const float* Wl1 = (const float*)d_in[2];
    const float* Wr1 = (const float*)d_in[3];
    const float* b1  = (const float*)d_in[4];
    const float* Wl2 = (const float*)d_in[5];
    const float* Wr2 = (const float*)d_in[6];
    const float* b2  = (const float*)d_in[7];
    float* out = (float*)d_out;

    int n = in_sizes[0] / 128;
    int E = in_sizes[1] / 2;

    static int smem_set = 0;
    if (!smem_set) {
        cudaFuncSetAttribute(k_fused, cudaFuncAttributeMaxDynamicSharedMemorySize,
                             SMEM_BYTES);
        smem_set = 1;
    }

    int nb = (n + SCAN_BLK - 1) / SCAN_BLK;

    k_prehist<<<(n * 32 + 255) / 256, 256>>>(x, ei, Wl1, Wr1, Wl2, Wr2, n, E);
    k_scan_scatter<<<nb, SCAN_BLK>>>(ei, n, E);
    k_agg16<<<(n * 32 + 255) / 256, 256>>>(n);
    k_fused<<<(n + 127) / 128, 256, SMEM_BYTES>>>(b1, n);     // launch 4 (profiled)
    k_final16<<<(n * 32 + 255) / 256, 256>>>(out, b2, n);
}

// round 11
// speedup vs baseline: 1.4005x; 1.0243x over previous
#include <cuda_runtime.h>
#include <cuda_fp16.h>
#include <cstdint>

// ---------------------------------------------------------------------------
// GraphSAGE 2-layer, N=100000, E=1600000, 128 -> 128 -> 64.
//   layer1: h1 = relu( mean_agg(x) @ Wl1 + x @ Wr1 + b1 )
//   layer2: out = mean_agg(h1 @ Wl2) + h1 @ Wr2 + b2   (agg is linear)
// 5 launches:
//   1 k_prehist      x->fp16, W->fp16 k-paired transposed, degree histogram
//   2 k_scan_scatter lookback scan + grid barrier + CSR scatter
//   3 k_agg16        fp16 warp-gather mean agg -> fp16
//   4 k_fused        fp16 m16n8k16 GEMM, 512 thr, cp.async + ldmatrix,
//                    both layers, h1 stays in smem
//   5 k_final16      fp16 gather + residual + bias (+ reset state for replay)
// ---------------------------------------------------------------------------

#define NNODES_MAX 100000
#define EDGES_MAX  1600000
#define SCAN_BLK   1024

__device__ int     d_deg[NNODES_MAX + 1];     // zeroed by k_final16 for replay
__device__ int     d_rowptr[NNODES_MAX + 1];
__device__ int     d_cur[NNODES_MAX + 1];
__device__ int     d_bsums[128];              // zeroed by k_final16
__device__ int     d_bflag[128];              // zeroed by k_final16
__device__ int     d_barrier;                 // zeroed by k_final16
__device__ int     d_adj[EDGES_MAX];
__device__ __align__(16) __half  d_x16[(size_t)NNODES_MAX * 128];
__device__ __align__(16) __half  d_agg16[(size_t)NNODES_MAX * 128];
__device__ __align__(16) uint32_t d_w1c[128 * 128];  // [n][k2] half2, K=256
__device__ __align__(16) uint32_t d_w2c[128 * 64];   // [n][k2] half2, K=128
__device__ __align__(16) __half  d_p16[(size_t)NNODES_MAX * 64];
__device__ __align__(16) float   d_q[(size_t)NNODES_MAX * 64];

// int32 edge arrays have random nonzero odd 32-bit words; int64 (<2^31) no.
__device__ __forceinline__ int detect_not64_block(const void* ei) {
    __shared__ int s_not64;
    if (threadIdx.x == 0) {
        const unsigned int* w = (const unsigned int*)ei;
        unsigned int o = 0;
#pragma unroll
        for (int j = 1; j < 32; j += 2) o |= w[j];
        s_not64 = (o != 0);
    }
    __syncthreads();
    return s_not64;
}

// ---------------------------------------------------------------------------
// 1) x -> fp16; W1/W2 -> fp16 k-paired col-major; degree histogram
// ---------------------------------------------------------------------------

__global__ void k_prehist(const float* __restrict__ x, const void* __restrict__ ei,
                          const float* __restrict__ W1l, const float* __restrict__ W1r,
                          const float* __restrict__ W2l, const float* __restrict__ W2r,
                          int n, int E) {
    int not64 = detect_not64_block(ei);
    int i = blockIdx.x * blockDim.x + threadIdx.x;
    if (i < n * 32) {                          // one float4 -> uint2 per thread
        float4 v = __ldg((const float4*)x + i);
        __half2 h0 = __floats2half2_rn(v.x, v.y);
        __half2 h1 = __floats2half2_rn(v.z, v.w);
        uint2 u;
        u.x = *(const unsigned int*)&h0;
        u.y = *(const unsigned int*)&h1;
        ((uint2*)d_x16)[i] = u;
    }
    if (i < E) {
        int dst = not64 ? ((const int*)ei)[E + i]
                        : (int)((const long long*)ei)[(size_t)E + i];
        atomicAdd(&d_deg[dst], 1);
    }
    // W1c: [n=128][k2=128], k = 2*k2; k<128 from W1l, else W1r
    if (i < 128 * 128) {
        int nn = i >> 7, k2 = i & 127, k = k2 * 2;
        float f0, f1;
        if (k < 128) { f0 = W1l[k * 128 + nn]; f1 = W1l[(k + 1) * 128 + nn]; }
        else         { f0 = W1r[(k - 128) * 128 + nn]; f1 = W1r[(k - 127) * 128 + nn]; }
        __half2 h = __floats2half2_rn(f0, f1);
        d_w1c[i] = *(const uint32_t*)&h;
    } else if (i < 128 * 128 + 128 * 64) {
        // W2c: [n=128][k2=64]; n<64 from W2l, else W2r
        int j = i - 128 * 128;
        int nn = j >> 6, k2 = j & 63, k = k2 * 2;
        float f0, f1;
        if (nn < 64) { f0 = W2l[k * 64 + nn]; f1 = W2l[(k + 1) * 64 + nn]; }
        else         { f0 = W2r[k * 64 + (nn - 64)]; f1 = W2r[(k + 1) * 64 + (nn - 64)]; }
        __half2 h = __floats2half2_rn(f0, f1);
        d_w2c[j] = *(const uint32_t*)&h;
    }
}

// ---------------------------------------------------------------------------
// 2) lookback scan over block sums + grid barrier + CSR scatter (one kernel;
//    98 blocks, all resident -> spins are deadlock-free)
// ---------------------------------------------------------------------------

__global__ void k_scan_scatter(const void* __restrict__ ei, int n, int E) {
    int not64 = detect_not64_block(ei);
    __shared__ int wsum[32];
    __shared__ int s_off;
    int b = blockIdx.x;
    int i = b * SCAN_BLK + threadIdx.x;
    int v = (i < n) ? d_deg[i] : 0;
    int lane = threadIdx.x & 31, w = threadIdx.x >> 5;
    int inc = v;
#pragma unroll
    for (int o = 1; o < 32; o <<= 1) {
        int t = __shfl_up_sync(0xffffffffu, inc, o);
        if (lane >= o) inc += t;
    }
    if (lane == 31) wsum[w] = inc;
    __syncthreads();
    if (w == 0) {
        int s = wsum[lane];
        int si = s;
#pragma unroll
        for (int o = 1; o < 32; o <<= 1) {
            int t = __shfl_up_sync(0xffffffffu, si, o);
            if (lane >= o) si += t;
        }
        wsum[lane] = si - s;
    }
    __syncthreads();
    int excl = inc - v + wsum[w];

    if (threadIdx.x == SCAN_BLK - 1) {
        d_bsums[b] = excl + v;
        __threadfence();
        *((volatile int*)&d_bflag[b]) = 1;
    }
    if (w == 0) {
        int sum = 0;
        for (int j = lane; j < b; j += 32) {
            while (*((volatile int*)&d_bflag[j]) == 0) __nanosleep(50);
            sum += *((volatile int*)&d_bsums[j]);
        }
#pragma unroll
        for (int o = 16; o > 0; o >>= 1) sum += __shfl_down_sync(0xffffffffu, sum, o);
        if (lane == 0) s_off = sum;
    }
    __syncthreads();
    if (i < n) {
        int t = excl + s_off;
        d_rowptr[i] = t;
        d_cur[i] = t;
    }

    // grid barrier: all cur[] must be written before any scatter
    __syncthreads();
    if (threadIdx.x == 0) {
        __threadfence();
        atomicAdd(&d_barrier, 1);
        while (*((volatile int*)&d_barrier) < gridDim.x) __nanosleep(100);
    }
    __syncthreads();

    int stride = gridDim.x * blockDim.x;
    for (int e = b * SCAN_BLK + threadIdx.x; e < E; e += stride) {
        int src, dst;
        if (not64) {
            const int* p = (const int*)ei;
            src = p[e];
            dst = p[E + e];
        } else {
            const long long* p = (const long long*)ei;
            src = (int)p[e];
            dst = (int)p[(size_t)E + e];
        }
        int pos = atomicAdd(&d_cur[dst], 1);
        d_adj[pos] = src;
    }
}

// ---------------------------------------------------------------------------
// 3) layer-1 aggregation: warp/node, fp16 feats, fp32 accumulate, fp16 out
// ---------------------------------------------------------------------------

__global__ void k_agg16(int n) {
    int gw = (blockIdx.x * blockDim.x + threadIdx.x) >> 5;
    if (gw >= n) return;
    int lane = threadIdx.x & 31;
    int start = d_rowptr[gw], deg = d_deg[gw];
    const uint2* base = (const uint2*)d_x16;    // 32 uint2 per 128-half row
    float ax = 0.f, ay = 0.f, az = 0.f, aw = 0.f;
    int j = 0;
    for (; j + 8 <= deg; j += 8) {
        int idx[8];
#pragma unroll
        for (int q = 0; q < 8; q++) idx[q] = d_adj[start + j + q];
        uint2 u[8];
#pragma unroll
        for (int q = 0; q < 8; q++) u[q] = __ldg(base + (size_t)idx[q] * 32 + lane);
#pragma unroll
        for (int q = 0; q < 8; q++) {
            float2 f0 = __half22float2(*(const __half2*)&u[q].x);
            float2 f1 = __half22float2(*(const __half2*)&u[q].y);
            ax += f0.x; ay += f0.y; az += f1.x; aw += f1.y;
        }
    }
    for (; j < deg; j++) {
        int nb = d_adj[start + j];
        uint2 u = __ldg(base + (size_t)nb * 32 + lane);
        float2 f0 = __half22float2(*(const __half2*)&u.x);
        float2 f1 = __half22float2(*(const __half2*)&u.y);
        ax += f0.x; ay += f0.y; az += f1.x; aw += f1.y;
    }
    float inv = 1.0f / (float)(deg > 0 ? deg : 1);
    __half2 h0 = __floats2half2_rn(ax * inv, ay * inv);
    __half2 h1 = __floats2half2_rn(az * inv, aw * inv);
    uint2 u;
    u.x = *(const unsigned int*)&h0;
    u.y = *(const unsigned int*)&h1;
    ((uint2*)d_agg16)[(size_t)gw * 32 + lane] = u;
}

// ---------------------------------------------------------------------------
// 5) out = mean_agg(p16) + q + b2 ; resets device state for next replay
// ---------------------------------------------------------------------------

__global__ void k_final16(float* __restrict__ out, const float* __restrict__ b2, int n) {
    int gw = (blockIdx.x * blockDim.x + threadIdx.x) >> 5;
    if (gw >= n) return;
    int lane = threadIdx.x & 31;
    int start = d_rowptr[gw], deg = d_deg[gw];
    const unsigned int* base = (const unsigned int*)d_p16;  // 32 uints per row
    float ax = 0.f, ay = 0.f;
    int j = 0;
    for (; j + 8 <= deg; j += 8) {
        int idx[8];
#pragma unroll
        for (int q = 0; q < 8; q++) idx[q] = d_adj[start + j + q];
        unsigned int u[8];
#pragma unroll
        for (int q = 0; q < 8; q++) u[q] = __ldg(base + (size_t)idx[q] * 32 + lane);
#pragma unroll
        for (int q = 0; q < 8; q++) {
            float2 f = __half22float2(*(const __half2*)&u[q]);
            ax += f.x; ay += f.y;
        }
    }
    for (; j < deg; j++) {
        int nb = d_adj[start + j];
        unsigned int u = __ldg(base + (size_t)nb * 32 + lane);
        float2 f = __half22float2(*(const __half2*)&u);
        ax += f.x; ay += f.y;
    }
    float inv = 1.0f / (float)(deg > 0 ? deg : 1);
    float2 q = *(const float2*)(d_q + (size_t)gw * 64 + 2 * lane);
    float2 bb = *(const float2*)(b2 + 2 * lane);
    float2 r;
    r.x = ax * inv + q.x + bb.x;
    r.y = ay * inv + q.y + bb.y;
    *(float2*)(out + (size_t)gw * 64 + 2 * lane) = r;

    // prep next run (deterministic across replays)
    if (lane == 0) d_deg[gw] = 0;
    if (blockIdx.x == 0 && threadIdx.x < 128) {
        d_bsums[threadIdx.x] = 0;
        d_bflag[threadIdx.x] = 0;
        if (threadIdx.x == 0) d_barrier = 0;
    }
}

// ---------------------------------------------------------------------------
// 4) fused fp16 m16n8k16 GEMM. BM=128, BN=128, BK=32 halves, 512 threads,
// 16 warps, warp tile 32x32, cp.async double-buffered tiles, ldmatrix frags.
//  phase1: acc = [agg16 | x16](K=256) @ W1c; h1 = relu(acc+b1) -> fp16 smem
//  phase2: [p|q] = h1(K=128) @ W2c; p -> fp16 d_p16, q -> fp32 d_q
// smem bytes: As0 10240 | As1 10240 | Bs0 10240 | Bs1 10240 | A2 34816
// ---------------------------------------------------------------------------

#define AST   20
#define BST   20
#define A2ST  68
#define AS0_B 0
#define AS1_B 10240
#define BS0_B 20480
#define BS1_B 30720
#define A2_B  40960
#define SMEM_BYTES (A2_B + 128 * A2ST * 4)   // 75776

__device__ __forceinline__ void mma_f16(float c[4],
                                        uint32_t a0, uint32_t a1, uint32_t a2, uint32_t a3,
                                        uint32_t b0, uint32_t b1) {
    asm volatile(
        "mma.sync.aligned.m16n8k16.row.col.f32.f16.f16.f32 "
        "{%0,%1,%2,%3},{%4,%5,%6,%7},{%8,%9},{%0,%1,%2,%3};"
        : "+f"(c[0]), "+f"(c[1]), "+f"(c[2]), "+f"(c[3])
        : "r"(a0), "r"(a1), "r"(a2), "r"(a3), "r"(b0), "r"(b1));
}

__device__ __forceinline__ void ldsm_x4(uint32_t& r0, uint32_t& r1,
                                        uint32_t& r2, uint32_t& r3, uint32_t addr) {
    asm volatile("ldmatrix.sync.aligned.m8n8.x4.shared.b16 {%0,%1,%2,%3}, [%4];"
                 : "=r"(r0), "=r"(r1), "=r"(r2), "=r"(r3) : "r"(addr));
}

__device__ __forceinline__ void cp16(uint32_t dst, const void* src, int sz) {
    asm volatile("cp.async.cg.shared.global [%0], [%1], 16, %2;"
                 :: "r"(dst), "l"(src), "r"(sz) : "memory");
}
#define CP_COMMIT() asm volatile("cp.async.commit_group;" ::: "memory")
#define CP_WAIT0()  asm volatile("cp.async.wait_group 0;" ::: "memory")
#define CP_WAIT1()  asm volatile("cp.async.wait_group 1;" ::: "memory")

__global__ __launch_bounds__(512, 2) void k_fused(const float* __restrict__ b1, int M) {
    extern __shared__ uint32_t smem[];
    const uint32_t sb = (uint32_t)__cvta_generic_to_shared(smem);

    const int tid = threadIdx.x;
    const int lane = tid & 31;
    const int warp = tid >> 5;
    const int wm = warp >> 2;          // 0..3: 32-row band
    const int wn = warp & 3;           // 0..3: 32-col band
    const int g = lane >> 2;
    const int t = lane & 3;
    const int row0 = blockIdx.x * 128;

    // ldmatrix lane-address components (verified against scalar mapping)
    const int arow = lane & 15;                       // A row within 16
    const int acolw = (lane >> 4) * 4;                // A k-word 0 or 4
    const int brow = (lane & 7) + ((lane >= 16) ? 8 : 0);
    const int bcolw = ((lane & 15) >= 8) ? 4 : 0;

    // cp.async coords: 512 threads cover 128 rows x 4 uint4
    const int ldrow = tid >> 2;
    const int ldc4 = tid & 3;
    const int grow = row0 + ldrow;
    const int avalid = (grow < M) ? 16 : 0;
    const size_t arowoff = (size_t)((grow < M) ? grow : 0) * 16;

    const uint4* agg4 = (const uint4*)d_agg16;
    const uint4* x4   = (const uint4*)d_x16;
    const uint4* w1   = (const uint4*)d_w1c;   // 32 uint4 per n
    const uint4* w2   = (const uint4*)d_w2c;   // 16 uint4 per n

    const uint32_t a_dst = sb + (uint32_t)(ldrow * AST + ldc4 * 4) * 4;
    const uint32_t b_dst = sb + (uint32_t)(ldrow * BST + ldc4 * 4) * 4;

    float acc[2][4][4];
#pragma unroll
    for (int mi = 0; mi < 2; mi++)
#pragma unroll
        for (int ni = 0; ni < 4; ni++)
#pragma unroll
            for (int r = 0; r < 4; r++) acc[mi][ni][r] = 0.f;

    // fragment compute over one staged ktile (A base/stride/k-offset, B base)
    auto mma_tiles = [&](uint32_t aBase, int astride, int kof, uint32_t bBase) {
#pragma unroll
        for (int ks = 0; ks < 2; ks++) {
            uint32_t a[2][4];
#pragma unroll
            for (int mi = 0; mi < 2; mi++) {
                uint32_t addr = aBase +
                    (uint32_t)(((wm * 32 + mi * 16 + arow) * astride) +
                               kof + ks * 8 + acolw) * 4;
                ldsm_x4(a[mi][0], a[mi][1], a[mi][2], a[mi][3], addr);
            }
            uint32_t bf[2][4];
#pragma unroll
            for (int pr = 0; pr < 2; pr++) {
                uint32_t addr = bBase +
                    (uint32_t)(((wn * 32 + pr * 16 + brow) * BST) +
                               ks * 8 + bcolw) * 4;
                ldsm_x4(bf[pr][0], bf[pr][1], bf[pr][2], bf[pr][3], addr);
            }
#pragma unroll
            for (int mi = 0; mi < 2; mi++)
#pragma unroll
                for (int ni = 0; ni < 4; ni++)
                    mma_f16(acc[mi][ni], a[mi][0], a[mi][1], a[mi][2], a[mi][3],
                            bf[ni >> 1][(ni & 1) * 2], bf[ni >> 1][(ni & 1) * 2 + 1]);
        }
    };

    auto loadA1 = [&](int kt, uint32_t bufoff) {
        const uint4* src = (kt < 4) ? (agg4 + arowoff + kt * 4 + ldc4)
                                    : (x4 + arowoff + (kt - 4) * 4 + ldc4);
        cp16(a_dst + bufoff, src, avalid);
    };
    auto loadB1 = [&](int kt, uint32_t bufoff) {
        cp16(b_dst + bufoff, w1 + ldrow * 32 + kt * 4 + ldc4, 16);
    };

    // ----- phase 1: K = 256, 8 ktiles, cp.async double-buffered -----
    loadA1(0, AS0_B);
    loadB1(0, BS0_B);
    CP_COMMIT();
#pragma unroll
    for (int kt = 0; kt < 8; kt++) {
        const uint32_t ab = (kt & 1) ? AS1_B : AS0_B;
        const uint32_t bb = (kt & 1) ? BS1_B : BS0_B;
        if (kt < 7) {
            loadA1(kt + 1, (kt & 1) ? AS0_B : AS1_B);
            loadB1(kt + 1, (kt & 1) ? BS0_B : BS1_B);
            CP_COMMIT();
            CP_WAIT1();
        } else {
            CP_WAIT0();
        }
        __syncthreads();
        mma_tiles(sb + ab, AST, 0, sb + bb);
        __syncthreads();
    }

    // prefetch W2 ktile 0 into Bs0 (overlaps epilogue)
    cp16(b_dst + BS0_B, w2 + ldrow * 16 + ldc4, 16);
    CP_COMMIT();

    // phase-1 epilogue: h1 = relu(acc + b1) -> fp16 A2 (k-paired)
    {
        uint32_t* A2w = smem + A2_B / 4;
#pragma unroll
        for (int mi = 0; mi < 2; mi++) {
#pragma unroll
            for (int ni = 0; ni < 4; ni++) {
                int rr = wm * 32 + mi * 16 + g;
                int cc = wn * 32 + ni * 8 + 2 * t;
                int ci = cc >> 1;
                float bb0 = b1[cc], bb1 = b1[cc + 1];
                __half2 h0 = __floats2half2_rn(fmaxf(acc[mi][ni][0] + bb0, 0.f),
                                               fmaxf(acc[mi][ni][1] + bb1, 0.f));
                __half2 h1 = __floats2half2_rn(fmaxf(acc[mi][ni][2] + bb0, 0.f),
                                               fmaxf(acc[mi][ni][3] + bb1, 0.f));
                A2w[rr * A2ST + ci] = *(const uint32_t*)&h0;
                A2w[(rr + 8) * A2ST + ci] = *(const uint32_t*)&h1;
            }
        }
    }
#pragma unroll
    for (int mi = 0; mi < 2; mi++)
#pragma unroll
        for (int ni = 0; ni < 4; ni++)
#pragma unroll
            for (int r = 0; r < 4; r++) acc[mi][ni][r] = 0.f;

    CP_WAIT0();
    __syncthreads();

    // ----- phase 2: K = 128, 4 ktiles (A2 resident, B double-buffered) -----
#pragma unroll
    for (int kt = 0; kt < 4; kt++) {
        const uint32_t bb = (kt & 1) ? BS1_B : BS0_B;
        if (kt < 3) {
            cp16(b_dst + ((kt & 1) ? BS0_B : BS1_B),
                 w2 + ldrow * 16 + (kt + 1) * 4 + ldc4, 16);
            CP_COMMIT();
            CP_WAIT1();
        } else {
            CP_WAIT0();
        }
        __syncthreads();
        mma_tiles(sb + A2_B, A2ST, kt * 16, sb + bb);
        __syncthreads();
    }

    // phase-2 epilogue: cols < 64 -> p fp16; cols >= 64 -> q fp32
#pragma unroll
    for (int mi = 0; mi < 2; mi++) {
#pragma unroll
        for (int ni = 0; ni < 4; ni++) {
            int r0 = row0 + wm * 32 + mi * 16 + g;
            int cc = wn * 32 + ni * 8 + 2 * t;
            if (cc < 64) {
                __half2 h0 = __floats2half2_rn(acc[mi][ni][0], acc[mi][ni][1]);
                __half2 h1 = __floats2half2_rn(acc[mi][ni][2], acc[mi][ni][3]);
                if (r0 < M)
                    *(__half2*)(d_p16 + (size_t)r0 * 64 + cc) = h0;
                if (r0 + 8 < M)
                    *(__half2*)(d_p16 + (size_t)(r0 + 8) * 64 + cc) = h1;
            } else {
                int cq = cc - 64;
                if (r0 < M)
                    *(float2*)(d_q + (size_t)r0 * 64 + cq) =
                        make_float2(acc[mi][ni][0], acc[mi][ni][1]);
                if (r0 + 8 < M)
                    *(float2*)(d_q + (size_t)(r0 + 8) * 64 + cq) =
                        make_float2(acc[mi][ni][2], acc[mi][ni][3]);
            }
        }
    }
}

// ---------------------------------------------------------------------------
// Launch
// ---------------------------------------------------------------------------

extern "C" void kernel_launch(void* const* d_in, const int* in_sizes, int n_in,
                              void* d_out, int out_size) {
    const float* x   = (const float*)d_in[0];
    const void*  ei  = d_in[1];
    const float* Wl1 = (const float*)d_in[2];
    const float* Wr1 = (const float*)d_in[3];
    const float* b1  = (const float*)d_in[4];
    const float* Wl2 = (const float*)d_in[5];
    const float* Wr2 = (const float*)d_in[6];
    const float* b2  = (const float*)d_in[7];
    float* out = (float*)d_out;

    int n = in_sizes[0] / 128;
    int E = in_sizes[1] / 2;

    static int smem_set = 0;
    if (!smem_set) {
        cudaFuncSetAttribute(k_fused, cudaFuncAttributeMaxDynamicSharedMemorySize,
                             SMEM_BYTES);
        smem_set = 1;
    }

    int nb = (n + SCAN_BLK - 1) / SCAN_BLK;

    k_prehist<<<(n * 32 + 255) / 256, 256>>>(x, ei, Wl1, Wr1, Wl2, Wr2, n, E);
    k_scan_scatter<<<nb, SCAN_BLK>>>(ei, n, E);
    k_agg16<<<(n * 32 + 255) / 256, 256>>>(n);
    k_fused<<<(n + 127) / 128, 512, SMEM_BYTES>>>(b1, n);     // launch 4 (profiled)
    k_final16<<<(n * 32 + 255) / 256, 256>>>(out, b2, n);
}

// round 12
// speedup vs baseline: 1.4875x; 1.0621x over previous
#include <cuda_runtime.h>
#include <cuda_fp16.h>
#include <cstdint>

// ---------------------------------------------------------------------------
// GraphSAGE 2-layer, N=100000, E=1600000, 128 -> 128 -> 64.
//   layer1: h1 = relu( mean_agg(x) @ Wl1 + x @ Wr1 + b1 )
//   layer2: out = mean_agg(h1 @ Wl2) + h1 @ Wr2 + b2   (agg is linear)
// 5 launches:
//   1 k_prehist      x->fp16, W->fp16 k-paired transposed, degree histogram
//   2 k_scan_scatter lookback scan + grid barrier + CSR scatter
//   3 k_agg16        fp16 warp-gather mean agg (depth-1 hadd2 pairing)
//   4 k_fused        fp16 m16n8k16 GEMM, 512 thr, 3-stage cp.async (1 sync/kt)
//   5 k_final16      fp16 gather + residual + bias (+ reset state for replay)
// ---------------------------------------------------------------------------

#define NNODES_MAX 100000
#define EDGES_MAX  1600000
#define SCAN_BLK   1024

__device__ int     d_deg[NNODES_MAX + 1];     // zeroed by k_final16 for replay
__device__ int     d_rowptr[NNODES_MAX + 1];
__device__ int     d_cur[NNODES_MAX + 1];
__device__ int     d_bsums[128];              // zeroed by k_final16
__device__ int     d_bflag[128];              // zeroed by k_final16
__device__ int     d_barrier;                 // zeroed by k_final16
__device__ int     d_adj[EDGES_MAX];
__device__ __align__(16) __half  d_x16[(size_t)NNODES_MAX * 128];
__device__ __align__(16) __half  d_agg16[(size_t)NNODES_MAX * 128];
__device__ __align__(16) uint32_t d_w1c[128 * 128];  // [n][k2] half2, K=256
__device__ __align__(16) uint32_t d_w2c[128 * 64];   // [n][k2] half2, K=128
__device__ __align__(16) __half  d_p16[(size_t)NNODES_MAX * 64];
__device__ __align__(16) float   d_q[(size_t)NNODES_MAX * 64];

// int32 edge arrays have random nonzero odd 32-bit words; int64 (<2^31) no.
__device__ __forceinline__ int detect_not64_block(const void* ei) {
    __shared__ int s_not64;
    if (threadIdx.x == 0) {
        const unsigned int* w = (const unsigned int*)ei;
        unsigned int o = 0;
#pragma unroll
        for (int j = 1; j < 32; j += 2) o |= w[j];
        s_not64 = (o != 0);
    }
    __syncthreads();
    return s_not64;
}

// ---------------------------------------------------------------------------
// 1) x -> fp16; W1/W2 -> fp16 k-paired col-major; degree histogram
// ---------------------------------------------------------------------------

__global__ void k_prehist(const float* __restrict__ x, const void* __restrict__ ei,
                          const float* __restrict__ W1l, const float* __restrict__ W1r,
                          const float* __restrict__ W2l, const float* __restrict__ W2r,
                          int n, int E) {
    int not64 = detect_not64_block(ei);
    int i = blockIdx.x * blockDim.x + threadIdx.x;
    if (i < n * 32) {                          // one float4 -> uint2 per thread
        float4 v = __ldg((const float4*)x + i);
        __half2 h0 = __floats2half2_rn(v.x, v.y);
        __half2 h1 = __floats2half2_rn(v.z, v.w);
        uint2 u;
        u.x = *(const unsigned int*)&h0;
        u.y = *(const unsigned int*)&h1;
        ((uint2*)d_x16)[i] = u;
    }
    if (i < E) {
        int dst = not64 ? ((const int*)ei)[E + i]
                        : (int)((const long long*)ei)[(size_t)E + i];
        atomicAdd(&d_deg[dst], 1);
    }
    // W1c: [n=128][k2=128], k = 2*k2; k<128 from W1l, else W1r
    if (i < 128 * 128) {
        int nn = i >> 7, k2 = i & 127, k = k2 * 2;
        float f0, f1;
        if (k < 128) { f0 = W1l[k * 128 + nn]; f1 = W1l[(k + 1) * 128 + nn]; }
        else         { f0 = W1r[(k - 128) * 128 + nn]; f1 = W1r[(k - 127) * 128 + nn]; }
        __half2 h = __floats2half2_rn(f0, f1);
        d_w1c[i] = *(const uint32_t*)&h;
    } else if (i < 128 * 128 + 128 * 64) {
        // W2c: [n=128][k2=64]; n<64 from W2l, else W2r
        int j = i - 128 * 128;
        int nn = j >> 6, k2 = j & 63, k = k2 * 2;
        float f0, f1;
        if (nn < 64) { f0 = W2l[k * 64 + nn]; f1 = W2l[(k + 1) * 64 + nn]; }
        else         { f0 = W2r[k * 64 + (nn - 64)]; f1 = W2r[(k + 1) * 64 + (nn - 64)]; }
        __half2 h = __floats2half2_rn(f0, f1);
        d_w2c[j] = *(const uint32_t*)&h;
    }
}

// ---------------------------------------------------------------------------
// 2) lookback scan over block sums + grid barrier + CSR scatter (one kernel;
//    98 blocks, all resident -> spins are deadlock-free)
// ---------------------------------------------------------------------------

__global__ void k_scan_scatter(const void* __restrict__ ei, int n, int E) {
    int not64 = detect_not64_block(ei);
    __shared__ int wsum[32];
    __shared__ int s_off;
    int b = blockIdx.x;
    int i = b * SCAN_BLK + threadIdx.x;
    int v = (i < n) ? d_deg[i] : 0;
    int lane = threadIdx.x & 31, w = threadIdx.x >> 5;
    int inc = v;
#pragma unroll
    for (int o = 1; o < 32; o <<= 1) {
        int t = __shfl_up_sync(0xffffffffu, inc, o);
        if (lane >= o) inc += t;
    }
    if (lane == 31) wsum[w] = inc;
    __syncthreads();
    if (w == 0) {
        int s = wsum[lane];
        int si = s;
#pragma unroll
        for (int o = 1; o < 32; o <<= 1) {
            int t = __shfl_up_sync(0xffffffffu, si, o);
            if (lane >= o) si += t;
        }
        wsum[lane] = si - s;
    }
    __syncthreads();
    int excl = inc - v + wsum[w];

    if (threadIdx.x == SCAN_BLK - 1) {
        d_bsums[b] = excl + v;
        __threadfence();
        *((volatile int*)&d_bflag[b]) = 1;
    }
    if (w == 0) {
        int sum = 0;
        for (int j = lane; j < b; j += 32) {
            while (*((volatile int*)&d_bflag[j]) == 0) __nanosleep(50);
            sum += *((volatile int*)&d_bsums[j]);
        }
#pragma unroll
        for (int o = 16; o > 0; o >>= 1) sum += __shfl_down_sync(0xffffffffu, sum, o);
        if (lane == 0) s_off = sum;
    }
    __syncthreads();
    if (i < n) {
        int t = excl + s_off;
        d_rowptr[i] = t;
        d_cur[i] = t;
    }

    // grid barrier: all cur[] must be written before any scatter
    __syncthreads();
    if (threadIdx.x == 0) {
        __threadfence();
        atomicAdd(&d_barrier, 1);
        while (*((volatile int*)&d_barrier) < gridDim.x) __nanosleep(100);
    }
    __syncthreads();

    int stride = gridDim.x * blockDim.x;
    for (int e = b * SCAN_BLK + threadIdx.x; e < E; e += stride) {
        int src, dst;
        if (not64) {
            const int* p = (const int*)ei;
            src = p[e];
            dst = p[E + e];
        } else {
            const long long* p = (const long long*)ei;
            src = (int)p[e];
            dst = (int)p[(size_t)E + e];
        }
        int pos = atomicAdd(&d_cur[dst], 1);
        d_adj[pos] = src;
    }
}

// ---------------------------------------------------------------------------
// 3) layer-1 aggregation: warp/node, fp16 feats, depth-1 hadd2 pairing,
//    fp32 accumulate, fp16 out
// ---------------------------------------------------------------------------

__global__ void k_agg16(int n) {
    int gw = (blockIdx.x * blockDim.x + threadIdx.x) >> 5;
    if (gw >= n) return;
    int lane = threadIdx.x & 31;
    int start = d_rowptr[gw], deg = d_deg[gw];
    const uint2* base = (const uint2*)d_x16;    // 32 uint2 per 128-half row
    float ax = 0.f, ay = 0.f, az = 0.f, aw = 0.f;
    int j = 0;
    for (; j + 8 <= deg; j += 8) {
        int idx[8];
#pragma unroll
        for (int q = 0; q < 8; q++) idx[q] = d_adj[start + j + q];
        uint2 u[8];
#pragma unroll
        for (int q = 0; q < 8; q++) u[q] = __ldg(base + (size_t)idx[q] * 32 + lane);
#pragma unroll
        for (int p = 0; p < 4; p++) {
            __half2 s0 = __hadd2(*(const __half2*)&u[2 * p].x,
                                 *(const __half2*)&u[2 * p + 1].x);
            __half2 s1 = __hadd2(*(const __half2*)&u[2 * p].y,
                                 *(const __half2*)&u[2 * p + 1].y);
            float2 f0 = __half22float2(s0);
            float2 f1 = __half22float2(s1);
            ax += f0.x; ay += f0.y; az += f1.x; aw += f1.y;
        }
    }
    for (; j + 2 <= deg; j += 2) {
        int na = d_adj[start + j], nb = d_adj[start + j + 1];
        uint2 ua = __ldg(base + (size_t)na * 32 + lane);
        uint2 ub = __ldg(base + (size_t)nb * 32 + lane);
        __half2 s0 = __hadd2(*(const __half2*)&ua.x, *(const __half2*)&ub.x);
        __half2 s1 = __hadd2(*(const __half2*)&ua.y, *(const __half2*)&ub.y);
        float2 f0 = __half22float2(s0);
        float2 f1 = __half22float2(s1);
        ax += f0.x; ay += f0.y; az += f1.x; aw += f1.y;
    }
    if (j < deg) {
        int nb = d_adj[start + j];
        uint2 u = __ldg(base + (size_t)nb * 32 + lane);
        float2 f0 = __half22float2(*(const __half2*)&u.x);
        float2 f1 = __half22float2(*(const __half2*)&u.y);
        ax += f0.x; ay += f0.y; az += f1.x; aw += f1.y;
    }
    float inv = 1.0f / (float)(deg > 0 ? deg : 1);
    __half2 h0 = __floats2half2_rn(ax * inv, ay * inv);
    __half2 h1 = __floats2half2_rn(az * inv, aw * inv);
    uint2 u;
    u.x = *(const unsigned int*)&h0;
    u.y = *(const unsigned int*)&h1;
    ((uint2*)d_agg16)[(size_t)gw * 32 + lane] = u;
}

// ---------------------------------------------------------------------------
// 5) out = mean_agg(p16) + q + b2 ; resets device state for next replay
// ---------------------------------------------------------------------------

__global__ void k_final16(float* __restrict__ out, const float* __restrict__ b2, int n) {
    int gw = (blockIdx.x * blockDim.x + threadIdx.x) >> 5;
    if (gw >= n) return;
    int lane = threadIdx.x & 31;
    int start = d_rowptr[gw], deg = d_deg[gw];
    const unsigned int* base = (const unsigned int*)d_p16;  // 32 uints per row
    float ax = 0.f, ay = 0.f;
    int j = 0;
    for (; j + 8 <= deg; j += 8) {
        int idx[8];
#pragma unroll
        for (int q = 0; q < 8; q++) idx[q] = d_adj[start + j + q];
        unsigned int u[8];
#pragma unroll
        for (int q = 0; q < 8; q++) u[q] = __ldg(base + (size_t)idx[q] * 32 + lane);
#pragma unroll
        for (int p = 0; p < 4; p++) {
            __half2 s = __hadd2(*(const __half2*)&u[2 * p],
                                *(const __half2*)&u[2 * p + 1]);
            float2 f = __half22float2(s);
            ax += f.x; ay += f.y;
        }
    }
    for (; j + 2 <= deg; j += 2) {
        int na = d_adj[start + j], nb = d_adj[start + j + 1];
        unsigned int ua = __ldg(base + (size_t)na * 32 + lane);
        unsigned int ub = __ldg(base + (size_t)nb * 32 + lane);
        __half2 s = __hadd2(*(const __half2*)&ua, *(const __half2*)&ub);
        float2 f = __half22float2(s);
        ax += f.x; ay += f.y;
    }
    if (j < deg) {
        int nb = d_adj[start + j];
        unsigned int u = __ldg(base + (size_t)nb * 32 + lane);
        float2 f = __half22float2(*(const __half2*)&u);
        ax += f.x; ay += f.y;
    }
    float inv = 1.0f / (float)(deg > 0 ? deg : 1);
    float2 q = *(const float2*)(d_q + (size_t)gw * 64 + 2 * lane);
    float2 bb = *(const float2*)(b2 + 2 * lane);
    float2 r;
    r.x = ax * inv + q.x + bb.x;
    r.y = ay * inv + q.y + bb.y;
    *(float2*)(out + (size_t)gw * 64 + 2 * lane) = r;

    // prep next run (deterministic across replays)
    if (lane == 0) d_deg[gw] = 0;
    if (blockIdx.x == 0 && threadIdx.x < 128) {
        d_bsums[threadIdx.x] = 0;
        d_bflag[threadIdx.x] = 0;
        if (threadIdx.x == 0) d_barrier = 0;
    }
}

// ---------------------------------------------------------------------------
// 4) fused fp16 m16n8k16 GEMM. BM=128, BN=128, BK=32 halves, 512 threads,
// 16 warps, warp tile 32x32, 3-stage cp.async pipeline (ONE sync per ktile),
// ldmatrix fragments.
//  phase1: acc = [agg16 | x16](K=256) @ W1c; h1 = relu(acc+b1) -> fp16 smem
//  phase2: [p|q] = h1(K=128) @ W2c; p -> fp16 d_p16, q -> fp32 d_q
// smem: 3 stages x (A 10240B + B 10240B) = 61440B, then A2 34816B.
// ---------------------------------------------------------------------------

#define AST   20
#define BST   20
#define A2ST  68
#define STGB  20480
#define BOFF  10240
#define A2_B  61440
#define SMEM_BYTES (A2_B + 128 * A2ST * 4)   // 96256

__device__ __forceinline__ void mma_f16(float c[4],
                                        uint32_t a0, uint32_t a1, uint32_t a2, uint32_t a3,
                                        uint32_t b0, uint32_t b1) {
    asm volatile(
        "mma.sync.aligned.m16n8k16.row.col.f32.f16.f16.f32 "
        "{%0,%1,%2,%3},{%4,%5,%6,%7},{%8,%9},{%0,%1,%2,%3};"
        : "+f"(c[0]), "+f"(c[1]), "+f"(c[2]), "+f"(c[3])
        : "r"(a0), "r"(a1), "r"(a2), "r"(a3), "r"(b0), "r"(b1));
}

__device__ __forceinline__ void ldsm_x4(uint32_t& r0, uint32_t& r1,
                                        uint32_t& r2, uint32_t& r3, uint32_t addr) {
    asm volatile("ldmatrix.sync.aligned.m8n8.x4.shared.b16 {%0,%1,%2,%3}, [%4];"
                 : "=r"(r0), "=r"(r1), "=r"(r2), "=r"(r3) : "r"(addr));
}

__device__ __forceinline__ void cp16(uint32_t dst, const void* src, int sz) {
    asm volatile("cp.async.cg.shared.global [%0], [%1], 16, %2;"
                 :: "r"(dst), "l"(src), "r"(sz) : "memory");
}
#define CP_COMMIT() asm volatile("cp.async.commit_group;" ::: "memory")
#define CP_WAIT0()  asm volatile("cp.async.wait_group 0;" ::: "memory")
#define CP_WAIT1()  asm volatile("cp.async.wait_group 1;" ::: "memory")

__global__ __launch_bounds__(512, 2) void k_fused(const float* __restrict__ b1, int M) {
    extern __shared__ uint32_t smem[];
    const uint32_t sb = (uint32_t)__cvta_generic_to_shared(smem);

    const int tid = threadIdx.x;
    const int lane = tid & 31;
    const int warp = tid >> 5;
    const int wm = warp >> 2;          // 0..3: 32-row band
    const int wn = warp & 3;           // 0..3: 32-col band
    const int g = lane >> 2;
    const int t = lane & 3;
    const int row0 = blockIdx.x * 128;

    // ldmatrix lane-address components (verified mapping)
    const int arow = lane & 15;
    const int acolw = (lane >> 4) * 4;
    const int brow = (lane & 7) + ((lane >= 16) ? 8 : 0);
    const int bcolw = ((lane & 15) >= 8) ? 4 : 0;

    // cp.async coords: 512 threads cover 128 rows x 4 uint4
    const int ldrow = tid >> 2;
    const int ldc4 = tid & 3;
    const int grow = row0 + ldrow;
    const int avalid = (grow < M) ? 16 : 0;
    const size_t arowoff = (size_t)((grow < M) ? grow : 0) * 16;

    const uint4* agg4 = (const uint4*)d_agg16;
    const uint4* x4   = (const uint4*)d_x16;
    const uint4* w1   = (const uint4*)d_w1c;   // 32 uint4 per n
    const uint4* w2   = (const uint4*)d_w2c;   // 16 uint4 per n

    const uint32_t a_dst = sb + (uint32_t)(ldrow * AST + ldc4 * 4) * 4;
    const uint32_t b_dst = sb + BOFF + (uint32_t)(ldrow * BST + ldc4 * 4) * 4;

    float acc[2][4][4];
#pragma unroll
    for (int mi = 0; mi < 2; mi++)
#pragma unroll
        for (int ni = 0; ni < 4; ni++)
#pragma unroll
            for (int r = 0; r < 4; r++) acc[mi][ni][r] = 0.f;

    auto mma_tiles = [&](uint32_t aBase, int astride, int kof, uint32_t bBase) {
#pragma unroll
        for (int ks = 0; ks < 2; ks++) {
            uint32_t a[2][4];
#pragma unroll
            for (int mi = 0; mi < 2; mi++) {
                uint32_t addr = aBase +
                    (uint32_t)(((wm * 32 + mi * 16 + arow) * astride) +
                               kof + ks * 8 + acolw) * 4;
                ldsm_x4(a[mi][0], a[mi][1], a[mi][2], a[mi][3], addr);
            }
            uint32_t bf[2][4];
#pragma unroll
            for (int pr = 0; pr < 2; pr++) {
                uint32_t addr = bBase +
                    (uint32_t)(((wn * 32 + pr * 16 + brow) * BST) +
                               ks * 8 + bcolw) * 4;
                ldsm_x4(bf[pr][0], bf[pr][1], bf[pr][2], bf[pr][3], addr);
            }
#pragma unroll
            for (int mi = 0; mi < 2; mi++)
#pragma unroll
                for (int ni = 0; ni < 4; ni++)
                    mma_f16(acc[mi][ni], a[mi][0], a[mi][1], a[mi][2], a[mi][3],
                            bf[ni >> 1][(ni & 1) * 2], bf[ni >> 1][(ni & 1) * 2 + 1]);
        }
    };

    auto loadA1 = [&](int kt, uint32_t stg) {
        const uint4* src = (kt < 4) ? (agg4 + arowoff + kt * 4 + ldc4)
                                    : (x4 + arowoff + (kt - 4) * 4 + ldc4);
        cp16(a_dst + stg * STGB, src, avalid);
    };
    auto loadB1 = [&](int kt, uint32_t stg) {
        cp16(b_dst + stg * STGB, w1 + ldrow * 32 + kt * 4 + ldc4, 16);
    };
    auto loadB2 = [&](int kt, uint32_t stg) {
        cp16(b_dst + stg * STGB, w2 + ldrow * 16 + kt * 4 + ldc4, 16);
    };

    // ----- phase 1: K = 256, 8 ktiles, 3-stage, 1 sync/ktile -----
    loadA1(0, 0); loadB1(0, 0); CP_COMMIT();
    loadA1(1, 1); loadB1(1, 1); CP_COMMIT();
#pragma unroll
    for (int kt = 0; kt < 8; kt++) {
        if (kt < 7) CP_WAIT1(); else CP_WAIT0();
        __syncthreads();                     // stage kt visible to all warps;
                                             // also: all reads of stage kt%3's
                                             // previous contents are done
        if (kt + 2 < 8) {
            loadA1(kt + 2, (kt + 2) % 3);
            loadB1(kt + 2, (kt + 2) % 3);
            CP_COMMIT();
        }
        const uint32_t s = (kt % 3) * STGB;
        mma_tiles(sb + s, AST, 0, sb + BOFF + s);
    }

    __syncthreads();                          // all phase-1 mma reads done

    // prefetch W2 ktiles 0,1 into B stages 0,1 (overlaps epilogue)
    loadB2(0, 0); CP_COMMIT();
    loadB2(1, 1); CP_COMMIT();

    // phase-1 epilogue: h1 = relu(acc + b1) -> fp16 A2 (k-paired)
    {
        uint32_t* A2w = smem + A2_B / 4;
#pragma unroll
        for (int mi = 0; mi < 2; mi++) {
#pragma unroll
            for (int ni = 0; ni < 4; ni++) {
                int rr = wm * 32 + mi * 16 + g;
                int cc = wn * 32 + ni * 8 + 2 * t;
                int ci = cc >> 1;
                float bb0 = b1[cc], bb1 = b1[cc + 1];
                __half2 h0 = __floats2half2_rn(fmaxf(acc[mi][ni][0] + bb0, 0.f),
                                               fmaxf(acc[mi][ni][1] + bb1, 0.f));
                __half2 h1 = __floats2half2_rn(fmaxf(acc[mi][ni][2] + bb0, 0.f),
                                               fmaxf(acc[mi][ni][3] + bb1, 0.f));
                A2w[rr * A2ST + ci] = *(const uint32_t*)&h0;
                A2w[(rr + 8) * A2ST + ci] = *(const uint32_t*)&h1;
            }
        }
    }
#pragma unroll
    for (int mi = 0; mi < 2; mi++)
#pragma unroll
        for (int ni = 0; ni < 4; ni++)
#pragma unroll
            for (int r = 0; r < 4; r++) acc[mi][ni][r] = 0.f;

    // ----- phase 2: K = 128, 4 ktiles, A2 resident, B 3-stage, 1 sync/kt -----
#pragma unroll
    for (int kt = 0; kt < 4; kt++) {
        if (kt < 3) CP_WAIT1(); else CP_WAIT0();
        __syncthreads();                     // also orders A2 writes (kt==0)
        if (kt + 2 < 4) { loadB2(kt + 2, (kt + 2) % 3); CP_COMMIT(); }
        mma_tiles(sb + A2_B, A2ST, kt * 16, sb + BOFF + (kt % 3) * STGB);
    }

    // phase-2 epilogue: cols < 64 -> p fp16; cols >= 64 -> q fp32
#pragma unroll
    for (int mi = 0; mi < 2; mi++) {
#pragma unroll
        for (int ni = 0; ni < 4; ni++) {
            int r0 = row0 + wm * 32 + mi * 16 + g;
            int cc = wn * 32 + ni * 8 + 2 * t;
            if (cc < 64) {
                __half2 h0 = __floats2half2_rn(acc[mi][ni][0], acc[mi][ni][1]);
                __half2 h1 = __floats2half2_rn(acc[mi][ni][2], acc[mi][ni][3]);
                if (r0 < M)
                    *(__half2*)(d_p16 + (size_t)r0 * 64 + cc) = h0;
                if (r0 + 8 < M)
                    *(__half2*)(d_p16 + (size_t)(r0 + 8) * 64 + cc) = h1;
            } else {
                int cq = cc - 64;
                if (r0 < M)
                    *(float2*)(d_q + (size_t)r0 * 64 + cq) =
                        make_float2(acc[mi][ni][0], acc[mi][ni][1]);
                if (r0 + 8 < M)
                    *(float2*)(d_q + (size_t)(r0 + 8) * 64 + cq) =
                        make_float2(acc[mi][ni][2], acc[mi][ni][3]);
            }
        }
    }
}

// ---------------------------------------------------------------------------
// Launch
// ---------------------------------------------------------------------------

extern "C" void kernel_launch(void* const* d_in, const int* in_sizes, int n_in,
                              void* d_out, int out_size) {
    const float* x   = (const float*)d_in[0];
    const void*  ei  = d_in[1];
    const float* Wl1 = (const float*)d_in[2];
    const float* Wr1 = (const float*)d_in[3];
    const float* b1  = (const float*)d_in[4];
    const float* Wl2 = (const float*)d_in[5];
    const float* Wr2 = (const float*)d_in[6];
    const float* b2  = (const float*)d_in[7];
    float* out = (float*)d_out;

    int n = in_sizes[0] / 128;
    int E = in_sizes[1] / 2;

    static int smem_set = 0;
    if (!smem_set) {
        cudaFuncSetAttribute(k_fused, cudaFuncAttributeMaxDynamicSharedMemorySize,
                             SMEM_BYTES);
        smem_set = 1;
    }

    int nb = (n + SCAN_BLK - 1) / SCAN_BLK;

    k_prehist<<<(n * 32 + 255) / 256, 256>>>(x, ei, Wl1, Wr1, Wl2, Wr2, n, E);
    k_scan_scatter<<<nb, SCAN_BLK>>>(ei, n, E);
    k_agg16<<<(n * 32 + 255) / 256, 256>>>(n);
    k_fused<<<(n + 127) / 128, 512, SMEM_BYTES>>>(b1, n);     // launch 4 (profiled)
    k_final16<<<(n * 32 + 255) / 256, 256>>>(out, b2, n);
}

// round 14
// speedup vs baseline: 1.4917x; 1.0028x over previous
#include <cuda_runtime.h>
#include <cuda_fp16.h>
#include <cstdint>

// ---------------------------------------------------------------------------
// GraphSAGE 2-layer, N=100000, E=1600000, 128 -> 128 -> 64.
//   layer1: h1 = relu( mean_agg(x) @ Wl1 + x @ Wr1 + b1 )
//   layer2: out = mean_agg(h1 @ Wl2) + h1 @ Wr2 + b2   (agg is linear)
// 5 launches:
//   1 k_prehist      x->fp16, W->fp16 k-paired transposed, degree histogram
//   2 k_scan_scatter lookback scan + grid barrier + CSR scatter
//   3 k_agg16        fp16 warp-gather mean agg (depth-2 hadd2 trees)
//   4 k_fused        fp16 m16n8k16 GEMM, 512 thr, 3-stage cp.async (1 sync/kt)
//   5 k_final16      fp16 gather + residual + bias (+ reset state for replay)
// NOTE: tcgen05 is NOT available (harness compiles PTX at compute_100, which
// rejects sm_100a-only instructions) — mma.sync is the tensor path here.
// ---------------------------------------------------------------------------

#define NNODES_MAX 100000
#define EDGES_MAX  1600000
#define SCAN_BLK   1024

__device__ int     d_deg[NNODES_MAX + 1];     // zeroed by k_final16 for replay
__device__ int     d_rowptr[NNODES_MAX + 1];
__device__ int     d_cur[NNODES_MAX + 1];
__device__ int     d_bsums[128];              // zeroed by k_final16
__device__ int     d_bflag[128];              // zeroed by k_final16
__device__ int     d_barrier;                 // zeroed by k_final16
__device__ int     d_adj[EDGES_MAX];
__device__ __align__(16) __half   d_x16[(size_t)NNODES_MAX * 128];
__device__ __align__(16) __half   d_agg16[(size_t)NNODES_MAX * 128];
__device__ __align__(16) uint32_t d_w1c[128 * 128];  // [n][k2] half2, K=256
__device__ __align__(16) uint32_t d_w2c[128 * 64];   // [n][k2] half2, K=128
__device__ __align__(16) __half   d_p16[(size_t)NNODES_MAX * 64];
__device__ __align__(16) float    d_q[(size_t)NNODES_MAX * 64];

// int32 edge arrays have random nonzero odd 32-bit words; int64 (<2^31) no.
__device__ __forceinline__ int detect_not64_block(const void* ei) {
    __shared__ int s_not64;
    if (threadIdx.x == 0) {
        const unsigned int* w = (const unsigned int*)ei;
        unsigned int o = 0;
#pragma unroll
        for (int j = 1; j < 32; j += 2) o |= w[j];
        s_not64 = (o != 0);
    }
    __syncthreads();
    return s_not64;
}

// ---------------------------------------------------------------------------
// 1) x -> fp16; W1/W2 -> fp16 k-paired col-major; degree histogram
// ---------------------------------------------------------------------------

__global__ void k_prehist(const float* __restrict__ x, const void* __restrict__ ei,
                          const float* __restrict__ W1l, const float* __restrict__ W1r,
                          const float* __restrict__ W2l, const float* __restrict__ W2r,
                          int n, int E) {
    int not64 = detect_not64_block(ei);
    int i = blockIdx.x * blockDim.x + threadIdx.x;
    if (i < n * 32) {                          // one float4 -> uint2 per thread
        float4 v = __ldg((const float4*)x + i);
        __half2 h0 = __floats2half2_rn(v.x, v.y);
        __half2 h1 = __floats2half2_rn(v.z, v.w);
        uint2 u;
        u.x = *(const unsigned int*)&h0;
        u.y = *(const unsigned int*)&h1;
        ((uint2*)d_x16)[i] = u;
    }
    if (i < E) {
        int dst = not64 ? ((const int*)ei)[E + i]
                        : (int)((const long long*)ei)[(size_t)E + i];
        atomicAdd(&d_deg[dst], 1);
    }
    // W1c: [n=128][k2=128], k = 2*k2; k<128 from W1l, else W1r
    if (i < 128 * 128) {
        int nn = i >> 7, k2 = i & 127, k = k2 * 2;
        float f0, f1;
        if (k < 128) { f0 = W1l[k * 128 + nn]; f1 = W1l[(k + 1) * 128 + nn]; }
        else         { f0 = W1r[(k - 128) * 128 + nn]; f1 = W1r[(k - 127) * 128 + nn]; }
        __half2 h = __floats2half2_rn(f0, f1);
        d_w1c[i] = *(const uint32_t*)&h;
    } else if (i < 128 * 128 + 128 * 64) {
        // W2c: [n=128][k2=64]; n<64 from W2l, else W2r
        int j = i - 128 * 128;
        int nn = j >> 6, k2 = j & 63, k = k2 * 2;
        float f0, f1;
        if (nn < 64) { f0 = W2l[k * 64 + nn]; f1 = W2l[(k + 1) * 64 + nn]; }
        else         { f0 = W2r[k * 64 + (nn - 64)]; f1 = W2r[(k + 1) * 64 + (nn - 64)]; }
        __half2 h = __floats2half2_rn(f0, f1);
        d_w2c[j] = *(const uint32_t*)&h;
    }
}

// ---------------------------------------------------------------------------
// 2) lookback scan over block sums + grid barrier + CSR scatter (one kernel;
//    98 blocks, all resident -> spins are deadlock-free)
// ---------------------------------------------------------------------------

__global__ void k_scan_scatter(const void* __restrict__ ei, int n, int E) {
    int not64 = detect_not64_block(ei);
    __shared__ int wsum[32];
    __shared__ int s_off;
    int b = blockIdx.x;
    int i = b * SCAN_BLK + threadIdx.x;
    int v = (i < n) ? d_deg[i] : 0;
    int lane = threadIdx.x & 31, w = threadIdx.x >> 5;
    int inc = v;
#pragma unroll
    for (int o = 1; o < 32; o <<= 1) {
        int t = __shfl_up_sync(0xffffffffu, inc, o);
        if (lane >= o) inc += t;
    }
    if (lane == 31) wsum[w] = inc;
    __syncthreads();
    if (w == 0) {
        int s = wsum[lane];
        int si = s;
#pragma unroll
        for (int o = 1; o < 32; o <<= 1) {
            int t = __shfl_up_sync(0xffffffffu, si, o);
            if (lane >= o) si += t;
        }
        wsum[lane] = si - s;
    }
    __syncthreads();
    int excl = inc - v + wsum[w];

    if (threadIdx.x == SCAN_BLK - 1) {
        d_bsums[b] = excl + v;
        __threadfence();
        *((volatile int*)&d_bflag[b]) = 1;
    }
    if (w == 0) {
        int sum = 0;
        for (int j = lane; j < b; j += 32) {
            while (*((volatile int*)&d_bflag[j]) == 0) __nanosleep(50);
            sum += *((volatile int*)&d_bsums[j]);
        }
#pragma unroll
        for (int o = 16; o > 0; o >>= 1) sum += __shfl_down_sync(0xffffffffu, sum, o);
        if (lane == 0) s_off = sum;
    }
    __syncthreads();
    if (i < n) {
        int t = excl + s_off;
        d_rowptr[i] = t;
        d_cur[i] = t;
    }

    // grid barrier: all cur[] must be written before any scatter
    __syncthreads();
    if (threadIdx.x == 0) {
        __threadfence();
        atomicAdd(&d_barrier, 1);
        while (*((volatile int*)&d_barrier) < gridDim.x) __nanosleep(100);
    }
    __syncthreads();

    int stride = gridDim.x * blockDim.x;
    for (int e = b * SCAN_BLK + threadIdx.x; e < E; e += stride) {
        int src, dst;
        if (not64) {
            const int* p = (const int*)ei;
            src = p[e];
            dst = p[E + e];
        } else {
            const long long* p = (const long long*)ei;
            src = (int)p[e];
            dst = (int)p[(size_t)E + e];
        }
        int pos = atomicAdd(&d_cur[dst], 1);
        d_adj[pos] = src;
    }
}

// ---------------------------------------------------------------------------
// 3) layer-1 aggregation: warp/node, fp16 feats, depth-2 hadd2 trees,
//    fp32 accumulate, fp16 out
// ---------------------------------------------------------------------------

#define H2(v) (*(const __half2*)&(v))

__global__ void k_agg16(int n) {
    int gw = (blockIdx.x * blockDim.x + threadIdx.x) >> 5;
    if (gw >= n) return;
    int lane = threadIdx.x & 31;
    int start = d_rowptr[gw], deg = d_deg[gw];
    const uint2* base = (const uint2*)d_x16;    // 32 uint2 per 128-half row
    float ax = 0.f, ay = 0.f, az = 0.f, aw = 0.f;
    int j = 0;
    for (; j + 8 <= deg; j += 8) {
        int idx[8];
#pragma unroll
        for (int q = 0; q < 8; q++) idx[q] = d_adj[start + j + q];
        uint2 u[8];
#pragma unroll
        for (int q = 0; q < 8; q++) u[q] = __ldg(base + (size_t)idx[q] * 32 + lane);
#pragma unroll
        for (int p = 0; p < 2; p++) {
            const uint2* g = u + p * 4;
            __half2 sx = __hadd2(__hadd2(H2(g[0].x), H2(g[1].x)),
                                 __hadd2(H2(g[2].x), H2(g[3].x)));
            __half2 sy = __hadd2(__hadd2(H2(g[0].y), H2(g[1].y)),
                                 __hadd2(H2(g[2].y), H2(g[3].y)));
            float2 f0 = __half22float2(sx);
            float2 f1 = __half22float2(sy);
            ax += f0.x; ay += f0.y; az += f1.x; aw += f1.y;
        }
    }
    for (; j + 4 <= deg; j += 4) {
        uint2 g[4];
#pragma unroll
        for (int q = 0; q < 4; q++)
            g[q] = __ldg(base + (size_t)d_adj[start + j + q] * 32 + lane);
        __half2 sx = __hadd2(__hadd2(H2(g[0].x), H2(g[1].x)),
                             __hadd2(H2(g[2].x), H2(g[3].x)));
        __half2 sy = __hadd2(__hadd2(H2(g[0].y), H2(g[1].y)),
                             __hadd2(H2(g[2].y), H2(g[3].y)));
        float2 f0 = __half22float2(sx);
        float2 f1 = __half22float2(sy);
        ax += f0.x; ay += f0.y; az += f1.x; aw += f1.y;
    }
    for (; j + 2 <= deg; j += 2) {
        int na = d_adj[start + j], nb = d_adj[start + j + 1];
        uint2 ua = __ldg(base + (size_t)na * 32 + lane);
        uint2 ub = __ldg(base + (size_t)nb * 32 + lane);
        __half2 s0 = __hadd2(H2(ua.x), H2(ub.x));
        __half2 s1 = __hadd2(H2(ua.y), H2(ub.y));
        float2 f0 = __half22float2(s0);
        float2 f1 = __half22float2(s1);
        ax += f0.x; ay += f0.y; az += f1.x; aw += f1.y;
    }
    if (j < deg) {
        int nb = d_adj[start + j];
        uint2 u = __ldg(base + (size_t)nb * 32 + lane);
        float2 f0 = __half22float2(H2(u.x));
        float2 f1 = __half22float2(H2(u.y));
        ax += f0.x; ay += f0.y; az += f1.x; aw += f1.y;
    }
    float inv = 1.0f / (float)(deg > 0 ? deg : 1);
    __half2 h0 = __floats2half2_rn(ax * inv, ay * inv);
    __half2 h1 = __floats2half2_rn(az * inv, aw * inv);
    uint2 u;
    u.x = *(const unsigned int*)&h0;
    u.y = *(const unsigned int*)&h1;
    ((uint2*)d_agg16)[(size_t)gw * 32 + lane] = u;
}

// ---------------------------------------------------------------------------
// 5) out = mean_agg(p16) + q + b2 ; resets device state for next replay
// ---------------------------------------------------------------------------

__global__ void k_final16(float* __restrict__ out, const float* __restrict__ b2, int n) {
    int gw = (blockIdx.x * blockDim.x + threadIdx.x) >> 5;
    if (gw >= n) return;
    int lane = threadIdx.x & 31;
    int start = d_rowptr[gw], deg = d_deg[gw];
    const unsigned int* base = (const unsigned int*)d_p16;  // 32 uints per row
    float ax = 0.f, ay = 0.f;
    int j = 0;
    for (; j + 8 <= deg; j += 8) {
        int idx[8];
#pragma unroll
        for (int q = 0; q < 8; q++) idx[q] = d_adj[start + j + q];
        unsigned int u[8];
#pragma unroll
        for (int q = 0; q < 8; q++) u[q] = __ldg(base + (size_t)idx[q] * 32 + lane);
#pragma unroll
        for (int p = 0; p < 2; p++) {
            const unsigned int* g = u + p * 4;
            __half2 s = __hadd2(__hadd2(H2(g[0]), H2(g[1])),
                                __hadd2(H2(g[2]), H2(g[3])));
            float2 f = __half22float2(s);
            ax += f.x; ay += f.y;
        }
    }
    for (; j + 4 <= deg; j += 4) {
        unsigned int g[4];
#pragma unroll
        for (int q = 0; q < 4; q++)
            g[q] = __ldg(base + (size_t)d_adj[start + j + q] * 32 + lane);
        __half2 s = __hadd2(__hadd2(H2(g[0]), H2(g[1])),
                            __hadd2(H2(g[2]), H2(g[3])));
        float2 f = __half22float2(s);
        ax += f.x; ay += f.y;
    }
    for (; j + 2 <= deg; j += 2) {
        int na = d_adj[start + j], nb = d_adj[start + j + 1];
        unsigned int ua = __ldg(base + (size_t)na * 32 + lane);
        unsigned int ub = __ldg(base + (size_t)nb * 32 + lane);
        __half2 s = __hadd2(H2(ua), H2(ub));
        float2 f = __half22float2(s);
        ax += f.x; ay += f.y;
    }
    if (j < deg) {
        int nb = d_adj[start + j];
        unsigned int u = __ldg(base + (size_t)nb * 32 + lane);
        float2 f = __half22float2(H2(u));
        ax += f.x; ay += f.y;
    }
    float inv = 1.0f / (float)(deg > 0 ? deg : 1);
    float2 q = *(const float2*)(d_q + (size_t)gw * 64 + 2 * lane);
    float2 bb = *(const float2*)(b2 + 2 * lane);
    float2 r;
    r.x = ax * inv + q.x + bb.x;
    r.y = ay * inv + q.y + bb.y;
    *(float2*)(out + (size_t)gw * 64 + 2 * lane) = r;

    // prep next run (deterministic across replays)
    if (lane == 0) d_deg[gw] = 0;
    if (blockIdx.x == 0 && threadIdx.x < 128) {
        d_bsums[threadIdx.x] = 0;
        d_bflag[threadIdx.x] = 0;
        if (threadIdx.x == 0) d_barrier = 0;
    }
}

// ---------------------------------------------------------------------------
// 4) fused fp16 m16n8k16 GEMM. BM=128, BN=128, BK=32 halves, 512 threads,
// 16 warps, warp tile 32x32, 3-stage cp.async pipeline (ONE sync per ktile),
// ldmatrix fragments.  (R12-winning version, unchanged.)
//  phase1: acc = [agg16 | x16](K=256) @ W1c; h1 = relu(acc+b1) -> fp16 smem
//  phase2: [p|q] = h1(K=128) @ W2c; p -> fp16 d_p16, q -> fp32 d_q
// smem: 3 stages x (A 10240B + B 10240B) = 61440B, then A2 34816B.
// ---------------------------------------------------------------------------

#define AST   20
#define BST   20
#define A2ST  68
#define STGB  20480
#define BOFF  10240
#define A2_B  61440
#define SMEM_BYTES (A2_B + 128 * A2ST * 4)   // 96256

__device__ __forceinline__ void mma_f16(float c[4],
                                        uint32_t a0, uint32_t a1, uint32_t a2, uint32_t a3,
                                        uint32_t b0, uint32_t b1) {
    asm volatile(
        "mma.sync.aligned.m16n8k16.row.col.f32.f16.f16.f32 "
        "{%0,%1,%2,%3},{%4,%5,%6,%7},{%8,%9},{%0,%1,%2,%3};"
        : "+f"(c[0]), "+f"(c[1]), "+f"(c[2]), "+f"(c[3])
        : "r"(a0), "r"(a1), "r"(a2), "r"(a3), "r"(b0), "r"(b1));
}

__device__ __forceinline__ void ldsm_x4(uint32_t& r0, uint32_t& r1,
                                        uint32_t& r2, uint32_t& r3, uint32_t addr) {
    asm volatile("ldmatrix.sync.aligned.m8n8.x4.shared.b16 {%0,%1,%2,%3}, [%4];"
                 : "=r"(r0), "=r"(r1), "=r"(r2), "=r"(r3) : "r"(addr));
}

__device__ __forceinline__ void cp16(uint32_t dst, const void* src, int sz) {
    asm volatile("cp.async.cg.shared.global [%0], [%1], 16, %2;"
                 :: "r"(dst), "l"(src), "r"(sz) : "memory");
}
#define CP_COMMIT() asm volatile("cp.async.commit_group;" ::: "memory")
#define CP_WAIT0()  asm volatile("cp.async.wait_group 0;" ::: "memory")
#define CP_WAIT1()  asm volatile("cp.async.wait_group 1;" ::: "memory")

__global__ __launch_bounds__(512, 2) void k_fused(const float* __restrict__ b1, int M) {
    extern __shared__ uint32_t smem[];
    const uint32_t sb = (uint32_t)__cvta_generic_to_shared(smem);

    const int tid = threadIdx.x;
    const int lane = tid & 31;
    const int warp = tid >> 5;
    const int wm = warp >> 2;          // 0..3: 32-row band
    const int wn = warp & 3;           // 0..3: 32-col band
    const int g = lane >> 2;
    const int t = lane & 3;
    const int row0 = blockIdx.x * 128;

    // ldmatrix lane-address components (verified mapping)
    const int arow = lane & 15;
    const int acolw = (lane >> 4) * 4;
    const int brow = (lane & 7) + ((lane >= 16) ? 8 : 0);
    const int bcolw = ((lane & 15) >= 8) ? 4 : 0;

    // cp.async coords: 512 threads cover 128 rows x 4 uint4
    const int ldrow = tid >> 2;
    const int ldc4 = tid & 3;
    const int grow = row0 + ldrow;
    const int avalid = (grow < M) ? 16 : 0;
    const size_t arowoff = (size_t)((grow < M) ? grow : 0) * 16;

    const uint4* agg4 = (const uint4*)d_agg16;
    const uint4* x4   = (const uint4*)d_x16;
    const uint4* w1   = (const uint4*)d_w1c;   // 32 uint4 per n
    const uint4* w2   = (const uint4*)d_w2c;   // 16 uint4 per n

    const uint32_t a_dst = sb + (uint32_t)(ldrow * AST + ldc4 * 4) * 4;
    const uint32_t b_dst = sb + BOFF + (uint32_t)(ldrow * BST + ldc4 * 4) * 4;

    float acc[2][4][4];
#pragma unroll
    for (int mi = 0; mi < 2; mi++)
#pragma unroll
        for (int ni = 0; ni < 4; ni++)
#pragma unroll
            for (int r = 0; r < 4; r++) acc[mi][ni][r] = 0.f;

    auto mma_tiles = [&](uint32_t aBase, int astride, int kof, uint32_t bBase) {
#pragma unroll
        for (int ks = 0; ks < 2; ks++) {
            uint32_t a[2][4];
#pragma unroll
            for (int mi = 0; mi < 2; mi++) {
                uint32_t addr = aBase +
                    (uint32_t)(((wm * 32 + mi * 16 + arow) * astride) +
                               kof + ks * 8 + acolw) * 4;
                ldsm_x4(a[mi][0], a[mi][1], a[mi][2], a[mi][3], addr);
            }
            uint32_t bf[2][4];
#pragma unroll
            for (int pr = 0; pr < 2; pr++) {
                uint32_t addr = bBase +
                    (uint32_t)(((wn * 32 + pr * 16 + brow) * BST) +
                               ks * 8 + bcolw) * 4;
                ldsm_x4(bf[pr][0], bf[pr][1], bf[pr][2], bf[pr][3], addr);
            }
#pragma unroll
            for (int mi = 0; mi < 2; mi++)
#pragma unroll
                for (int ni = 0; ni < 4; ni++)
                    mma_f16(acc[mi][ni], a[mi][0], a[mi][1], a[mi][2], a[mi][3],
                            bf[ni >> 1][(ni & 1) * 2], bf[ni >> 1][(ni & 1) * 2 + 1]);
        }
    };

    auto loadA1 = [&](int kt, uint32_t stg) {
        const uint4* src = (kt < 4) ? (agg4 + arowoff + kt * 4 + ldc4)
                                    : (x4 + arowoff + (kt - 4) * 4 + ldc4);
        cp16(a_dst + stg * STGB, src, avalid);
    };
    auto loadB1 = [&](int kt, uint32_t stg) {
        cp16(b_dst + stg * STGB, w1 + ldrow * 32 + kt * 4 + ldc4, 16);
    };
    auto loadB2 = [&](int kt, uint32_t stg) {
        cp16(b_dst + stg * STGB, w2 + ldrow * 16 + kt * 4 + ldc4, 16);
    };

    // ----- phase 1: K = 256, 8 ktiles, 3-stage, 1 sync/ktile -----
    loadA1(0, 0); loadB1(0, 0); CP_COMMIT();
    loadA1(1, 1); loadB1(1, 1); CP_COMMIT();
#pragma unroll
    for (int kt = 0; kt < 8; kt++) {
        if (kt < 7) CP_WAIT1(); else CP_WAIT0();
        __syncthreads();
        if (kt + 2 < 8) {
            loadA1(kt + 2, (kt + 2) % 3);
            loadB1(kt + 2, (kt + 2) % 3);
            CP_COMMIT();
        }
        const uint32_t s = (kt % 3) * STGB;
        mma_tiles(sb + s, AST, 0, sb + BOFF + s);
    }

    __syncthreads();

    // prefetch W2 ktiles 0,1 into B stages 0,1 (overlaps epilogue)
    loadB2(0, 0); CP_COMMIT();
    loadB2(1, 1); CP_COMMIT();

    // phase-1 epilogue: h1 = relu(acc + b1) -> fp16 A2 (k-paired)
    {
        uint32_t* A2w = smem + A2_B / 4;
#pragma unroll
        for (int mi = 0; mi < 2; mi++) {
#pragma unroll
            for (int ni = 0; ni < 4; ni++) {
                int rr = wm * 32 + mi * 16 + g;
                int cc = wn * 32 + ni * 8 + 2 * t;
                int ci = cc >> 1;
                float bb0 = b1[cc], bb1 = b1[cc + 1];
                __half2 h0 = __floats2half2_rn(fmaxf(acc[mi][ni][0] + bb0, 0.f),
                                               fmaxf(acc[mi][ni][1] + bb1, 0.f));
                __half2 h1 = __floats2half2_rn(fmaxf(acc[mi][ni][2] + bb0, 0.f),
                                               fmaxf(acc[mi][ni][3] + bb1, 0.f));
                A2w[rr * A2ST + ci] = *(const uint32_t*)&h0;
                A2w[(rr + 8) * A2ST + ci] = *(const uint32_t*)&h1;
            }
        }
    }
#pragma unroll
    for (int mi = 0; mi < 2; mi++)
#pragma unroll
        for (int ni = 0; ni < 4; ni++)
#pragma unroll
            for (int r = 0; r < 4; r++) acc[mi][ni][r] = 0.f;

    // ----- phase 2: K = 128, 4 ktiles, A2 resident, B 3-stage, 1 sync/kt -----
#pragma unroll
    for (int kt = 0; kt < 4; kt++) {
        if (kt < 3) CP_WAIT1(); else CP_WAIT0();
        __syncthreads();                     // also orders A2 writes (kt==0)
        if (kt + 2 < 4) { loadB2(kt + 2, (kt + 2) % 3); CP_COMMIT(); }
        mma_tiles(sb + A2_B, A2ST, kt * 16, sb + BOFF + (kt % 3) * STGB);
    }

    // phase-2 epilogue: cols < 64 -> p fp16; cols >= 64 -> q fp32
#pragma unroll
    for (int mi = 0; mi < 2; mi++) {
#pragma unroll
        for (int ni = 0; ni < 4; ni++) {
            int r0 = row0 + wm * 32 + mi * 16 + g;
            int cc = wn * 32 + ni * 8 + 2 * t;
            if (cc < 64) {
                __half2 h0 = __floats2half2_rn(acc[mi][ni][0], acc[mi][ni][1]);
                __half2 h1 = __floats2half2_rn(acc[mi][ni][2], acc[mi][ni][3]);
                if (r0 < M)
                    *(__half2*)(d_p16 + (size_t)r0 * 64 + cc) = h0;
                if (r0 + 8 < M)
                    *(__half2*)(d_p16 + (size_t)(r0 + 8) * 64 + cc) = h1;
            } else {
                int cq = cc - 64;
                if (r0 < M)
                    *(float2*)(d_q + (size_t)r0 * 64 + cq) =
                        make_float2(acc[mi][ni][0], acc[mi][ni][1]);
                if (r0 + 8 < M)
                    *(float2*)(d_q + (size_t)(r0 + 8) * 64 + cq) =
                        make_float2(acc[mi][ni][2], acc[mi][ni][3]);
            }
        }
    }
}

// ---------------------------------------------------------------------------
// Launch
// ---------------------------------------------------------------------------

extern "C" void kernel_launch(void* const* d_in, const int* in_sizes, int n_in,
                              void* d_out, int out_size) {
    const float* x   = (const float*)d_in[0];
    const void*  ei  = d_in[1];
    const float* Wl1 = (const float*)d_in[2];
    const float* Wr1 = (const float*)d_in[3];
    const float* b1  = (const float*)d_in[4];
    const float* Wl2 = (const float*)d_in[5];
    const float* Wr2 = (const float*)d_in[6];
    const float* b2  = (const float*)d_in[7];
    float* out = (float*)d_out;

    int n = in_sizes[0] / 128;
    int E = in_sizes[1] / 2;

    static int smem_set = 0;
    if (!smem_set) {
        cudaFuncSetAttribute(k_fused, cudaFuncAttributeMaxDynamicSharedMemorySize,
                             SMEM_BYTES);
        smem_set = 1;
    }

    int nb = (n + SCAN_BLK - 1) / SCAN_BLK;

    k_prehist<<<(n * 32 + 255) / 256, 256>>>(x, ei, Wl1, Wr1, Wl2, Wr2, n, E);
    k_scan_scatter<<<nb, SCAN_BLK>>>(ei, n, E);
    k_agg16<<<(n * 32 + 255) / 256, 256>>>(n);
    k_fused<<<(n + 127) / 128, 512, SMEM_BYTES>>>(b1, n);     // launch 4 (profiled)
    k_final16<<<(n * 32 + 255) / 256, 256>>>(out, b2, n);
}